// round 7
// baseline (speedup 1.0000x reference)
#include <cuda_runtime.h>
#include <cuda_bf16.h>
#include <cstdint>
#include <math.h>

// Problem constants
#define BB   4
#define SS   2048
#define DD   1024
#define HH   16
#define HD   64
#define DQKV 3072
#define MM   (BB*SS)          // 8192
#define GK   1024

// GEMM tiling
#define BM 128
#define BN 128
#define BK 32
#define NKT (GK/BK)           // 32
#define ROWH 40               // padded row stride in halfs (80B)
#define MATH (BM*ROWH)
#define STAGEH (4*MATH)

// Flash smem layout: 3-stage KV ring (Khi,Klo,Vhi,Vlo per stage)
#define FROWH 72                      // K/V row stride in halfs (144B)
#define FMATB (64*FROWH*2)            // 9216 B per 64x64 bf16 matrix
#define FKVB  (4*FMATB)               // 36864 B per stage
#define FLASH_SMEM (3*FKVB)           // 110592 B -> still 2 CTAs/SM
#define NFT (SS/64)                   // 32 key tiles

// Scratch (allocation-free: device globals)
__device__ __nv_bfloat16 g_ahi[(size_t)MM * GK];
__device__ __nv_bfloat16 g_alo[(size_t)MM * GK];
__device__ __nv_bfloat16 g_whi[(size_t)DQKV * GK];
__device__ __nv_bfloat16 g_wlo[(size_t)DQKV * GK];
__device__ __nv_bfloat16 g_qh[(size_t)MM * DD];   // [b,h,s,d]
__device__ __nv_bfloat16 g_ql[(size_t)MM * DD];
__device__ __nv_bfloat16 g_kh[(size_t)MM * DD];
__device__ __nv_bfloat16 g_kl[(size_t)MM * DD];
__device__ __nv_bfloat16 g_vh[(size_t)MM * DD];
__device__ __nv_bfloat16 g_vl[(size_t)MM * DD];

// ---------------------------------------------------------------------------
// PTX helpers (sm_80-portable: cp.async, ldmatrix, mma.sync)
// ---------------------------------------------------------------------------
__device__ __forceinline__ uint32_t smem_u32(const void* p) {
    uint32_t a;
    asm("{ .reg .u64 t; cvta.to.shared.u64 t, %1; cvt.u32.u64 %0, t; }"
        : "=r"(a) : "l"(p));
    return a;
}
__device__ __forceinline__ void cp_async16(uint32_t dst, const void* src) {
    asm volatile("cp.async.cg.shared.global [%0], [%1], 16;" :: "r"(dst), "l"(src));
}
__device__ __forceinline__ void ldmx4(uint32_t* r, uint32_t addr) {
    asm volatile("ldmatrix.sync.aligned.m8n8.x4.shared.b16 {%0,%1,%2,%3}, [%4];"
                 : "=r"(r[0]), "=r"(r[1]), "=r"(r[2]), "=r"(r[3]) : "r"(addr));
}
__device__ __forceinline__ void ldmx4t(uint32_t* r, uint32_t addr) {
    asm volatile("ldmatrix.sync.aligned.m8n8.x4.trans.shared.b16 {%0,%1,%2,%3}, [%4];"
                 : "=r"(r[0]), "=r"(r[1]), "=r"(r[2]), "=r"(r[3]) : "r"(addr));
}
__device__ __forceinline__ void mma_bf16(float* d, const uint32_t* a, const uint32_t* b) {
    asm volatile(
        "mma.sync.aligned.m16n8k16.row.col.f32.bf16.bf16.f32 "
        "{%0,%1,%2,%3}, {%4,%5,%6,%7}, {%8,%9}, {%0,%1,%2,%3};"
        : "+f"(d[0]), "+f"(d[1]), "+f"(d[2]), "+f"(d[3])
        : "r"(a[0]), "r"(a[1]), "r"(a[2]), "r"(a[3]), "r"(b[0]), "r"(b[1]));
}
__device__ __forceinline__ void split2(float x, float y, uint32_t& hi, uint32_t& lo) {
    __nv_bfloat16 hx = __float2bfloat16(x);
    __nv_bfloat16 hy = __float2bfloat16(y);
    __nv_bfloat16 lx = __float2bfloat16(x - __bfloat162float(hx));
    __nv_bfloat16 ly = __float2bfloat16(y - __bfloat162float(hy));
    __nv_bfloat162 H(hx, hy), L(lx, ly);
    hi = *reinterpret_cast<uint32_t*>(&H);
    lo = *reinterpret_cast<uint32_t*>(&L);
}

// ---------------------------------------------------------------------------
// fp32 -> (hi, lo) bf16 split (bulk)
// ---------------------------------------------------------------------------
__global__ __launch_bounds__(256) void convert_kernel(
    const float* __restrict__ in, __nv_bfloat16* __restrict__ hi,
    __nv_bfloat16* __restrict__ lo, int n4)
{
    int i = blockIdx.x * blockDim.x + threadIdx.x;
    if (i >= n4) return;
    float4 v = *(const float4*)(in + (size_t)i * 4);
    uint32_t h0, l0, h1, l1;
    split2(v.x, v.y, h0, l0);
    split2(v.z, v.w, h1, l1);
    uint32_t* hp = (uint32_t*)(hi + (size_t)i * 4);
    uint32_t* lp = (uint32_t*)(lo + (size_t)i * 4);
    hp[0] = h0; hp[1] = h1;
    lp[0] = l0; lp[1] = l1;
}

// ---------------------------------------------------------------------------
// HMMA GEMM: C = A @ W^T + bias. mode 0: fp32 C. mode 1: QKV epilogue ->
// write q(*0.125)/k/v as hi/lo bf16 in [b,h,s,d] layout to device globals.
// ---------------------------------------------------------------------------
__global__ __launch_bounds__(256, 2) void gemm_mma_kernel(
    const __nv_bfloat16* __restrict__ Ahi, const __nv_bfloat16* __restrict__ Alo,
    const __nv_bfloat16* __restrict__ Whi, const __nv_bfloat16* __restrict__ Wlo,
    const float* __restrict__ bias, float* __restrict__ C, int N, int mode)
{
    extern __shared__ __nv_bfloat16 smg[];
    const uint32_t sb = smem_u32(smg);
    const int tid  = threadIdx.x;
    const int wid  = tid >> 5;
    const int lane = tid & 31;
    const int m0 = blockIdx.y * BM;
    const int n0 = blockIdx.x * BN;
    const int warp_m = (wid >> 2) * 64;
    const int warp_n = (wid & 3) * 32;

    float acc[4][4][4];
#pragma unroll
    for (int i = 0; i < 4; i++)
#pragma unroll
        for (int j = 0; j < 4; j++)
#pragma unroll
            for (int r = 0; r < 4; r++) acc[i][j][r] = 0.f;

    const __nv_bfloat16* gsrc[4] = {Ahi, Alo, Whi, Wlo};

    auto load_stage = [&](int kt, int st) {
        const int kcol = kt * BK;
#pragma unroll
        for (int t = 0; t < 8; t++) {
            int c   = tid + t * 256;
            int mat = c >> 9;
            int idx = c & 511;
            int row = idx >> 2;
            int c16 = idx & 3;
            int grow = (mat < 2 ? m0 : n0) + row;
            const __nv_bfloat16* src = gsrc[mat] + (size_t)grow * GK + kcol + c16 * 8;
            uint32_t dst = sb + (uint32_t)(st * STAGEH + mat * MATH + row * ROWH + c16 * 8) * 2;
            cp_async16(dst, src);
        }
        asm volatile("cp.async.commit_group;" ::: "memory");
    };

    load_stage(0, 0);

    for (int kt = 0; kt < NKT; kt++) {
        const int st = kt & 1;
        if (kt + 1 < NKT) {
            load_stage(kt + 1, st ^ 1);
            asm volatile("cp.async.wait_group 1;" ::: "memory");
        } else {
            asm volatile("cp.async.wait_group 0;" ::: "memory");
        }
        __syncthreads();

        const uint32_t stb = sb + (uint32_t)(st * STAGEH) * 2;
        const uint32_t aHi = stb;
        const uint32_t aLo = stb + MATH * 2;
        const uint32_t wHi = stb + 2 * MATH * 2;
        const uint32_t wLo = stb + 3 * MATH * 2;

#pragma unroll
        for (int ks = 0; ks < 2; ks++) {
            const int kk = ks * 16;
            uint32_t ah[4][4], al[4][4], bh[4][2], bl[4][2];
#pragma unroll
            for (int i = 0; i < 4; i++) {
                uint32_t off = (uint32_t)((warp_m + i * 16 + (lane & 15)) * ROWH
                                          + kk + (lane >> 4) * 8) * 2;
                ldmx4(ah[i], aHi + off);
                ldmx4(al[i], aLo + off);
            }
#pragma unroll
            for (int jp2 = 0; jp2 < 2; jp2++) {
                int g = lane >> 3;
                uint32_t off = (uint32_t)((warp_n + (2 * jp2 + (g >> 1)) * 8
                                           + (lane & 7)) * ROWH
                                          + kk + (g & 1) * 8) * 2;
                uint32_t r4[4];
                ldmx4(r4, wHi + off);
                bh[2 * jp2][0] = r4[0]; bh[2 * jp2][1] = r4[1];
                bh[2 * jp2 + 1][0] = r4[2]; bh[2 * jp2 + 1][1] = r4[3];
                ldmx4(r4, wLo + off);
                bl[2 * jp2][0] = r4[0]; bl[2 * jp2][1] = r4[1];
                bl[2 * jp2 + 1][0] = r4[2]; bl[2 * jp2 + 1][1] = r4[3];
            }
#pragma unroll
            for (int i = 0; i < 4; i++)
#pragma unroll
                for (int j = 0; j < 4; j++) mma_bf16(acc[i][j], ah[i], bh[j]);
#pragma unroll
            for (int i = 0; i < 4; i++)
#pragma unroll
                for (int j = 0; j < 4; j++) mma_bf16(acc[i][j], ah[i], bl[j]);
#pragma unroll
            for (int i = 0; i < 4; i++)
#pragma unroll
                for (int j = 0; j < 4; j++) mma_bf16(acc[i][j], al[i], bh[j]);
        }
        __syncthreads();
    }

    if (mode == 0) {
#pragma unroll
        for (int i = 0; i < 4; i++) {
#pragma unroll
            for (int j = 0; j < 4; j++) {
                int m = m0 + warp_m + i * 16 + (lane >> 2);
                int n = n0 + warp_n + j * 8 + (lane & 3) * 2;
                float2 bv = *(const float2*)(bias + n);
                float2 o0 = { acc[i][j][0] + bv.x, acc[i][j][1] + bv.y };
                float2 o1 = { acc[i][j][2] + bv.x, acc[i][j][3] + bv.y };
                *(float2*)(C + (size_t)m * N + n) = o0;
                *(float2*)(C + (size_t)(m + 8) * N + n) = o1;
            }
        }
    } else {
#pragma unroll
        for (int i = 0; i < 4; i++) {
#pragma unroll
            for (int j = 0; j < 4; j++) {
                int m = m0 + warp_m + i * 16 + (lane >> 2);
                int n = n0 + warp_n + j * 8 + (lane & 3) * 2;
                float2 bv = *(const float2*)(bias + n);
                int sel = n >> 10;
                int hh  = (n & 1023) >> 6;
                int d   = n & 63;
                float sc = (sel == 0) ? 0.125f : 1.0f;
                __nv_bfloat16 *dh, *dl;
                if (sel == 0)      { dh = g_qh; dl = g_ql; }
                else if (sel == 1) { dh = g_kh; dl = g_kl; }
                else               { dh = g_vh; dl = g_vl; }
#pragma unroll
                for (int rr = 0; rr < 2; rr++) {
                    int mm = m + rr * 8;
                    float vx = (acc[i][j][rr * 2 + 0] + bv.x) * sc;
                    float vy = (acc[i][j][rr * 2 + 1] + bv.y) * sc;
                    uint32_t hp, lp;
                    split2(vx, vy, hp, lp);
                    size_t idx = (((size_t)(mm >> 11) * HH + hh) * SS + (mm & 2047)) * HD + d;
                    *(uint32_t*)(dh + idx) = hp;
                    *(uint32_t*)(dl + idx) = lp;
                }
            }
        }
    }
}
static constexpr int SMEM_GEMM = 2 * STAGEH * 2;  // 81920 B

// ---------------------------------------------------------------------------
// Flash attention on HMMA, fixed-reference softmax, fine-grained key-group
// pipelining: per 16-key group g: QK(24 MMA) -> exp(8) -> split(4) ->
// bias prefetch into freed s regs -> PV(24 MMA). 3-stage KV ring, one
// __syncthreads per tile. Grid (BB, HH, SS/128); 256 thr; 2 CTAs/SM.
// ---------------------------------------------------------------------------
__global__ __launch_bounds__(256, 2) void flash_mma_kernel(
    const __nv_bfloat16* __restrict__ Qh, const __nv_bfloat16* __restrict__ Ql,
    const __nv_bfloat16* __restrict__ Kh, const __nv_bfloat16* __restrict__ Kl,
    const __nv_bfloat16* __restrict__ Vh, const __nv_bfloat16* __restrict__ Vl,
    const float* __restrict__ bias,
    __nv_bfloat16* __restrict__ AOh, __nv_bfloat16* __restrict__ AOl)
{
    extern __shared__ char smc[];
    const uint32_t sb = smem_u32(smc);
    const int tid = threadIdx.x, wid = tid >> 5, lane = tid & 31;
    const int b = blockIdx.x, h = blockIdx.y, q0 = blockIdx.z * 128;
    const int warp_m = wid * 16;
    const size_t bh = ((size_t)b * HH + h) * SS;

    // Q fragments straight from gmem (reused over all 32 k-tiles)
    uint32_t qfh[4][4], qfl[4][4];
    {
        size_t rA = (bh + q0 + warp_m + (lane >> 2)) * HD;
        size_t rB = rA + 8 * HD;
        int c0 = 2 * (lane & 3);
#pragma unroll
        for (int t = 0; t < 4; t++) {
            qfh[t][0] = *(const uint32_t*)(Qh + rA + 16 * t + c0);
            qfh[t][1] = *(const uint32_t*)(Qh + rB + 16 * t + c0);
            qfh[t][2] = *(const uint32_t*)(Qh + rA + 16 * t + 8 + c0);
            qfh[t][3] = *(const uint32_t*)(Qh + rB + 16 * t + 8 + c0);
            qfl[t][0] = *(const uint32_t*)(Ql + rA + 16 * t + c0);
            qfl[t][1] = *(const uint32_t*)(Ql + rB + 16 * t + c0);
            qfl[t][2] = *(const uint32_t*)(Ql + rA + 16 * t + 8 + c0);
            qfl[t][3] = *(const uint32_t*)(Ql + rB + 16 * t + 8 + c0);
        }
    }

    // bias row pointers for this thread's fragment rows
    const float* bp0 = bias + ((size_t)h * SS + q0 + warp_m + (lane >> 2)) * SS
                       + 2 * (lane & 3);
    const float* bp1 = bp0 + 8 * SS;

    float O[8][4];
#pragma unroll
    for (int j = 0; j < 8; j++)
#pragma unroll
        for (int r = 0; r < 4; r++) O[j][r] = 0.f;
    float lA = 0.f, lB = 0.f;

    // prefetch bias tile 0 into s
    float s[8][4];
#pragma unroll
    for (int j = 0; j < 8; j++) {
        float2 b0 = *(const float2*)(bp0 + 8 * j);
        float2 b1 = *(const float2*)(bp1 + 8 * j);
        s[j][0] = b0.x; s[j][1] = b0.y;
        s[j][2] = b1.x; s[j][3] = b1.y;
    }

    auto load_stage = [&](int kt) {
        if (kt < NFT) {
            uint32_t base = sb + (kt % 3) * FKVB;
            int k0 = kt * 64;
#pragma unroll
            for (int t = 0; t < 8; t++) {
                int mat = t >> 1;
                int idx = ((t & 1) << 8) + tid;          // 0..511
                int row = idx >> 3, ch = idx & 7;
                const __nv_bfloat16* src = (mat == 0) ? Kh : (mat == 1) ? Kl
                                         : (mat == 2) ? Vh : Vl;
                cp_async16(base + mat * FMATB + (uint32_t)(row * FROWH + ch * 8) * 2,
                           src + (bh + k0 + row) * HD + ch * 8);
            }
        }
        asm volatile("cp.async.commit_group;" ::: "memory");
    };

    load_stage(0);
    load_stage(1);

    const int krow = ((lane >> 4) & 1) * 8 + (lane & 7);
    const int kcol = ((lane >> 3) & 1) * 8;
    const int vrow = ((lane >> 3) & 1) * 8 + (lane & 7);
    const int vcol = ((lane >> 4) & 1) * 8;

    for (int kt = 0; kt < NFT; kt++) {
        // One barrier per tile: all warps done reading stage (kt-1)%3,
        // which load_stage(kt+2) will overwrite.
        __syncthreads();
        load_stage(kt + 2);
        asm volatile("cp.async.wait_group 2;" ::: "memory");  // stage kt ready

        const uint32_t kvb = sb + (kt % 3) * FKVB;

#pragma unroll
        for (int g = 0; g < 4; g++) {          // 16-key group pipeline
            // ---- QK: s[2g],s[2g+1] (+= over 4 d-chunks, 3-term) ----
#pragma unroll
            for (int dt = 0; dt < 4; dt++) {
                uint32_t addr = kvb + (uint32_t)((g * 16 + krow) * FROWH
                                                 + 16 * dt + kcol) * 2;
                uint32_t k4h[4], k4l[4];
                ldmx4(k4h, addr);
                ldmx4(k4l, addr + FMATB);
                mma_bf16(s[2 * g],     qfh[dt], k4h);
                mma_bf16(s[2 * g + 1], qfh[dt], k4h + 2);
                mma_bf16(s[2 * g],     qfh[dt], k4l);
                mma_bf16(s[2 * g + 1], qfh[dt], k4l + 2);
                mma_bf16(s[2 * g],     qfl[dt], k4h);
                mma_bf16(s[2 * g + 1], qfl[dt], k4h + 2);
            }

            // ---- exp + partial row sums ----
            float p0 = __expf(s[2 * g][0]),     p1 = __expf(s[2 * g][1]);
            float p2 = __expf(s[2 * g][2]),     p3 = __expf(s[2 * g][3]);
            float p4 = __expf(s[2 * g + 1][0]), p5 = __expf(s[2 * g + 1][1]);
            float p6 = __expf(s[2 * g + 1][2]), p7 = __expf(s[2 * g + 1][3]);
            lA += p0 + p1 + p4 + p5;
            lB += p2 + p3 + p6 + p7;

            // ---- pack P group (C-frag layout == A-frag layout) ----
            uint32_t pfh[4], pfl[4];
            split2(p0, p1, pfh[0], pfl[0]);
            split2(p2, p3, pfh[1], pfl[1]);
            split2(p4, p5, pfh[2], pfl[2]);
            split2(p6, p7, pfh[3], pfl[3]);

            // ---- s[2g..2g+1] now dead: prefetch next tile's bias group ----
            if (kt + 1 < NFT) {
                const int kn = (kt + 1) * 64 + 16 * g;
                float2 b0 = *(const float2*)(bp0 + kn);
                float2 b1 = *(const float2*)(bp1 + kn);
                s[2 * g][0] = b0.x; s[2 * g][1] = b0.y;
                s[2 * g][2] = b1.x; s[2 * g][3] = b1.y;
                b0 = *(const float2*)(bp0 + kn + 8);
                b1 = *(const float2*)(bp1 + kn + 8);
                s[2 * g + 1][0] = b0.x; s[2 * g + 1][1] = b0.y;
                s[2 * g + 1][2] = b1.x; s[2 * g + 1][3] = b1.y;
            }

            // ---- PV for this key group: O[d] += P(g) V(g,d), 3-term ----
#pragma unroll
            for (int jp = 0; jp < 4; jp++) {
                uint32_t addr = kvb + 2 * FMATB
                    + (uint32_t)((16 * g + vrow) * FROWH + 16 * jp + vcol) * 2;
                uint32_t v4h[4], v4l[4];
                ldmx4t(v4h, addr);
                ldmx4t(v4l, addr + FMATB);
                mma_bf16(O[2 * jp],     pfh, v4h);
                mma_bf16(O[2 * jp + 1], pfh, v4h + 2);
                mma_bf16(O[2 * jp],     pfh, v4l);
                mma_bf16(O[2 * jp + 1], pfh, v4l + 2);
                mma_bf16(O[2 * jp],     pfl, v4h);
                mma_bf16(O[2 * jp + 1], pfl, v4h + 2);
            }
        }
    }

    // ---- final row-sum reduction (once, not per tile) ----
    lA += __shfl_xor_sync(0xffffffffu, lA, 1);
    lA += __shfl_xor_sync(0xffffffffu, lA, 2);
    lB += __shfl_xor_sync(0xffffffffu, lB, 1);
    lB += __shfl_xor_sync(0xffffffffu, lB, 2);

    // ---- epilogue: normalize, split hi/lo, write out-proj A buffers ----
    float iA = 1.f / lA, iB = 1.f / lB;
    size_t oA = ((size_t)b * SS + q0 + warp_m + (lane >> 2)) * DD + h * HD;
    size_t oB = oA + 8 * DD;
#pragma unroll
    for (int j = 0; j < 8; j++) {
        int d = 8 * j + 2 * (lane & 3);
        uint32_t hp, lp;
        split2(O[j][0] * iA, O[j][1] * iA, hp, lp);
        *(uint32_t*)(AOh + oA + d) = hp;
        *(uint32_t*)(AOl + oA + d) = lp;
        split2(O[j][2] * iB, O[j][3] * iB, hp, lp);
        *(uint32_t*)(AOh + oB + d) = hp;
        *(uint32_t*)(AOl + oB + d) = lp;
    }
}

// ---------------------------------------------------------------------------
extern "C" void kernel_launch(void* const* d_in, const int* in_sizes, int n_in,
                              void* d_out, int out_size)
{
    (void)in_sizes; (void)n_in; (void)out_size;
    const float* x         = (const float*)d_in[0];
    const float* attn_bias = (const float*)d_in[1];
    const float* qkv_w     = (const float*)d_in[2];
    const float* qkv_b     = (const float*)d_in[3];
    const float* out_w     = (const float*)d_in[4];
    const float* out_b     = (const float*)d_in[5];
    float* out = (float*)d_out;

    __nv_bfloat16 *ahi, *alo, *whi, *wlo, *qh, *ql, *kh, *kl, *vh, *vl;
    cudaGetSymbolAddress((void**)&ahi, g_ahi);
    cudaGetSymbolAddress((void**)&alo, g_alo);
    cudaGetSymbolAddress((void**)&whi, g_whi);
    cudaGetSymbolAddress((void**)&wlo, g_wlo);
    cudaGetSymbolAddress((void**)&qh,  g_qh);
    cudaGetSymbolAddress((void**)&ql,  g_ql);
    cudaGetSymbolAddress((void**)&kh,  g_kh);
    cudaGetSymbolAddress((void**)&kl,  g_kl);
    cudaGetSymbolAddress((void**)&vh,  g_vh);
    cudaGetSymbolAddress((void**)&vl,  g_vl);

    cudaFuncSetAttribute(gemm_mma_kernel,
                         cudaFuncAttributeMaxDynamicSharedMemorySize, SMEM_GEMM);
    cudaFuncSetAttribute(flash_mma_kernel,
                         cudaFuncAttributeMaxDynamicSharedMemorySize, FLASH_SMEM);

    // 1) split x and qkv_w into bf16 hi/lo
    {
        int n4 = MM * GK / 4;
        convert_kernel<<<(n4 + 255) / 256, 256>>>(x, ahi, alo, n4);
        int w4 = DQKV * GK / 4;
        convert_kernel<<<(w4 + 255) / 256, 256>>>(qkv_w, whi, wlo, w4);
    }
    // 2) QKV projection; epilogue emits q/k/v hi-lo bf16 in [b,h,s,d]
    gemm_mma_kernel<<<dim3(DQKV / BN, MM / BM), 256, SMEM_GEMM>>>(
        ahi, alo, whi, wlo, qkv_b, out /*unused*/, DQKV, 1);

    // 3) Flash attention on tensor cores -> ahi/alo ([b*s][d] hi/lo)
    flash_mma_kernel<<<dim3(BB, HH, SS / 128), 256, FLASH_SMEM>>>(
        qh, ql, kh, kl, vh, vl, attn_bias, ahi, alo);

    // 4) split out_w
    {
        int w4 = DD * DD / 4;
        convert_kernel<<<(w4 + 255) / 256, 256>>>(out_w, whi, wlo, w4);
    }
    // 5) Output projection -> d_out
    gemm_mma_kernel<<<dim3(DD / BN, MM / BM), 256, SMEM_GEMM>>>(
        ahi, alo, whi, wlo, out_b, out, DD, 0);
}

// round 8
// speedup vs baseline: 1.0212x; 1.0212x over previous
#include <cuda_runtime.h>
#include <cuda_bf16.h>
#include <cstdint>
#include <math.h>

// Problem constants
#define BB   4
#define SS   2048
#define DD   1024
#define HH   16
#define HD   64
#define DQKV 3072
#define MM   (BB*SS)          // 8192
#define GK   1024

// GEMM tiling
#define BM 128
#define BN 128
#define BK 32
#define NKT (GK/BK)           // 32
#define ROWH 40               // padded row stride in halfs (80B)
#define MATH (BM*ROWH)
#define STAGEH (4*MATH)

// Flash smem layout: 3-stage KV ring (Khi,Klo,Vhi,Vlo per stage)
#define FROWH 72                      // K/V row stride in halfs (144B)
#define FMATB (64*FROWH*2)            // 9216 B per 64x64 bf16 matrix
#define FKVB  (4*FMATB)               // 36864 B per stage
#define FLASH_SMEM (3*FKVB)           // 110592 B -> 2 CTAs/SM
#define NFT (SS/64)                   // 32 key tiles

// Scratch (allocation-free: device globals)
__device__ __nv_bfloat16 g_ahi[(size_t)MM * GK];
__device__ __nv_bfloat16 g_alo[(size_t)MM * GK];
__device__ __nv_bfloat16 g_whi[(size_t)DQKV * GK];
__device__ __nv_bfloat16 g_wlo[(size_t)DQKV * GK];
__device__ __nv_bfloat16 g_qh[(size_t)MM * DD];   // [b,h,s,d]
__device__ __nv_bfloat16 g_ql[(size_t)MM * DD];
__device__ __nv_bfloat16 g_kh[(size_t)MM * DD];
__device__ __nv_bfloat16 g_kl[(size_t)MM * DD];
__device__ __nv_bfloat16 g_vh[(size_t)MM * DD];
__device__ __nv_bfloat16 g_vl[(size_t)MM * DD];

// ---------------------------------------------------------------------------
// PTX helpers (sm_80-portable: cp.async, ldmatrix, mma.sync)
// ---------------------------------------------------------------------------
__device__ __forceinline__ uint32_t smem_u32(const void* p) {
    uint32_t a;
    asm("{ .reg .u64 t; cvta.to.shared.u64 t, %1; cvt.u32.u64 %0, t; }"
        : "=r"(a) : "l"(p));
    return a;
}
__device__ __forceinline__ void cp_async16(uint32_t dst, const void* src) {
    asm volatile("cp.async.cg.shared.global [%0], [%1], 16;" :: "r"(dst), "l"(src));
}
__device__ __forceinline__ void ldmx4(uint32_t* r, uint32_t addr) {
    asm volatile("ldmatrix.sync.aligned.m8n8.x4.shared.b16 {%0,%1,%2,%3}, [%4];"
                 : "=r"(r[0]), "=r"(r[1]), "=r"(r[2]), "=r"(r[3]) : "r"(addr));
}
__device__ __forceinline__ void ldmx4t(uint32_t* r, uint32_t addr) {
    asm volatile("ldmatrix.sync.aligned.m8n8.x4.trans.shared.b16 {%0,%1,%2,%3}, [%4];"
                 : "=r"(r[0]), "=r"(r[1]), "=r"(r[2]), "=r"(r[3]) : "r"(addr));
}
__device__ __forceinline__ void mma_bf16(float* d, const uint32_t* a, const uint32_t* b) {
    asm volatile(
        "mma.sync.aligned.m16n8k16.row.col.f32.bf16.bf16.f32 "
        "{%0,%1,%2,%3}, {%4,%5,%6,%7}, {%8,%9}, {%0,%1,%2,%3};"
        : "+f"(d[0]), "+f"(d[1]), "+f"(d[2]), "+f"(d[3])
        : "r"(a[0]), "r"(a[1]), "r"(a[2]), "r"(a[3]), "r"(b[0]), "r"(b[1]));
}
__device__ __forceinline__ void split2(float x, float y, uint32_t& hi, uint32_t& lo) {
    __nv_bfloat16 hx = __float2bfloat16(x);
    __nv_bfloat16 hy = __float2bfloat16(y);
    __nv_bfloat16 lx = __float2bfloat16(x - __bfloat162float(hx));
    __nv_bfloat16 ly = __float2bfloat16(y - __bfloat162float(hy));
    __nv_bfloat162 H(hx, hy), L(lx, ly);
    hi = *reinterpret_cast<uint32_t*>(&H);
    lo = *reinterpret_cast<uint32_t*>(&L);
}

// ---------------------------------------------------------------------------
// fp32 -> (hi, lo) bf16 split (bulk)
// ---------------------------------------------------------------------------
__global__ __launch_bounds__(256) void convert_kernel(
    const float* __restrict__ in, __nv_bfloat16* __restrict__ hi,
    __nv_bfloat16* __restrict__ lo, int n4)
{
    int i = blockIdx.x * blockDim.x + threadIdx.x;
    if (i >= n4) return;
    float4 v = *(const float4*)(in + (size_t)i * 4);
    uint32_t h0, l0, h1, l1;
    split2(v.x, v.y, h0, l0);
    split2(v.z, v.w, h1, l1);
    uint32_t* hp = (uint32_t*)(hi + (size_t)i * 4);
    uint32_t* lp = (uint32_t*)(lo + (size_t)i * 4);
    hp[0] = h0; hp[1] = h1;
    lp[0] = l0; lp[1] = l1;
}

// ---------------------------------------------------------------------------
// HMMA GEMM: C = A @ W^T + bias. mode 0: fp32 C. mode 1: QKV epilogue ->
// write q(*0.125)/k/v as hi/lo bf16 in [b,h,s,d] layout to device globals.
// ---------------------------------------------------------------------------
__global__ __launch_bounds__(256, 2) void gemm_mma_kernel(
    const __nv_bfloat16* __restrict__ Ahi, const __nv_bfloat16* __restrict__ Alo,
    const __nv_bfloat16* __restrict__ Whi, const __nv_bfloat16* __restrict__ Wlo,
    const float* __restrict__ bias, float* __restrict__ C, int N, int mode)
{
    extern __shared__ __nv_bfloat16 smg[];
    const uint32_t sb = smem_u32(smg);
    const int tid  = threadIdx.x;
    const int wid  = tid >> 5;
    const int lane = tid & 31;
    const int m0 = blockIdx.y * BM;
    const int n0 = blockIdx.x * BN;
    const int warp_m = (wid >> 2) * 64;
    const int warp_n = (wid & 3) * 32;

    float acc[4][4][4];
#pragma unroll
    for (int i = 0; i < 4; i++)
#pragma unroll
        for (int j = 0; j < 4; j++)
#pragma unroll
            for (int r = 0; r < 4; r++) acc[i][j][r] = 0.f;

    const __nv_bfloat16* gsrc[4] = {Ahi, Alo, Whi, Wlo};

    auto load_stage = [&](int kt, int st) {
        const int kcol = kt * BK;
#pragma unroll
        for (int t = 0; t < 8; t++) {
            int c   = tid + t * 256;
            int mat = c >> 9;
            int idx = c & 511;
            int row = idx >> 2;
            int c16 = idx & 3;
            int grow = (mat < 2 ? m0 : n0) + row;
            const __nv_bfloat16* src = gsrc[mat] + (size_t)grow * GK + kcol + c16 * 8;
            uint32_t dst = sb + (uint32_t)(st * STAGEH + mat * MATH + row * ROWH + c16 * 8) * 2;
            cp_async16(dst, src);
        }
        asm volatile("cp.async.commit_group;" ::: "memory");
    };

    load_stage(0, 0);

    for (int kt = 0; kt < NKT; kt++) {
        const int st = kt & 1;
        if (kt + 1 < NKT) {
            load_stage(kt + 1, st ^ 1);
            asm volatile("cp.async.wait_group 1;" ::: "memory");
        } else {
            asm volatile("cp.async.wait_group 0;" ::: "memory");
        }
        __syncthreads();

        const uint32_t stb = sb + (uint32_t)(st * STAGEH) * 2;
        const uint32_t aHi = stb;
        const uint32_t aLo = stb + MATH * 2;
        const uint32_t wHi = stb + 2 * MATH * 2;
        const uint32_t wLo = stb + 3 * MATH * 2;

#pragma unroll
        for (int ks = 0; ks < 2; ks++) {
            const int kk = ks * 16;
            uint32_t ah[4][4], al[4][4], bh[4][2], bl[4][2];
#pragma unroll
            for (int i = 0; i < 4; i++) {
                uint32_t off = (uint32_t)((warp_m + i * 16 + (lane & 15)) * ROWH
                                          + kk + (lane >> 4) * 8) * 2;
                ldmx4(ah[i], aHi + off);
                ldmx4(al[i], aLo + off);
            }
#pragma unroll
            for (int jp2 = 0; jp2 < 2; jp2++) {
                int g = lane >> 3;
                uint32_t off = (uint32_t)((warp_n + (2 * jp2 + (g >> 1)) * 8
                                           + (lane & 7)) * ROWH
                                          + kk + (g & 1) * 8) * 2;
                uint32_t r4[4];
                ldmx4(r4, wHi + off);
                bh[2 * jp2][0] = r4[0]; bh[2 * jp2][1] = r4[1];
                bh[2 * jp2 + 1][0] = r4[2]; bh[2 * jp2 + 1][1] = r4[3];
                ldmx4(r4, wLo + off);
                bl[2 * jp2][0] = r4[0]; bl[2 * jp2][1] = r4[1];
                bl[2 * jp2 + 1][0] = r4[2]; bl[2 * jp2 + 1][1] = r4[3];
            }
#pragma unroll
            for (int i = 0; i < 4; i++)
#pragma unroll
                for (int j = 0; j < 4; j++) mma_bf16(acc[i][j], ah[i], bh[j]);
#pragma unroll
            for (int i = 0; i < 4; i++)
#pragma unroll
                for (int j = 0; j < 4; j++) mma_bf16(acc[i][j], ah[i], bl[j]);
#pragma unroll
            for (int i = 0; i < 4; i++)
#pragma unroll
                for (int j = 0; j < 4; j++) mma_bf16(acc[i][j], al[i], bh[j]);
        }
        __syncthreads();
    }

    if (mode == 0) {
#pragma unroll
        for (int i = 0; i < 4; i++) {
#pragma unroll
            for (int j = 0; j < 4; j++) {
                int m = m0 + warp_m + i * 16 + (lane >> 2);
                int n = n0 + warp_n + j * 8 + (lane & 3) * 2;
                float2 bv = *(const float2*)(bias + n);
                float2 o0 = { acc[i][j][0] + bv.x, acc[i][j][1] + bv.y };
                float2 o1 = { acc[i][j][2] + bv.x, acc[i][j][3] + bv.y };
                *(float2*)(C + (size_t)m * N + n) = o0;
                *(float2*)(C + (size_t)(m + 8) * N + n) = o1;
            }
        }
    } else {
#pragma unroll
        for (int i = 0; i < 4; i++) {
#pragma unroll
            for (int j = 0; j < 4; j++) {
                int m = m0 + warp_m + i * 16 + (lane >> 2);
                int n = n0 + warp_n + j * 8 + (lane & 3) * 2;
                float2 bv = *(const float2*)(bias + n);
                int sel = n >> 10;
                int hh  = (n & 1023) >> 6;
                int d   = n & 63;
                float sc = (sel == 0) ? 0.125f : 1.0f;
                __nv_bfloat16 *dh, *dl;
                if (sel == 0)      { dh = g_qh; dl = g_ql; }
                else if (sel == 1) { dh = g_kh; dl = g_kl; }
                else               { dh = g_vh; dl = g_vl; }
#pragma unroll
                for (int rr = 0; rr < 2; rr++) {
                    int mm = m + rr * 8;
                    float vx = (acc[i][j][rr * 2 + 0] + bv.x) * sc;
                    float vy = (acc[i][j][rr * 2 + 1] + bv.y) * sc;
                    uint32_t hp, lp;
                    split2(vx, vy, hp, lp);
                    size_t idx = (((size_t)(mm >> 11) * HH + hh) * SS + (mm & 2047)) * HD + d;
                    *(uint32_t*)(dh + idx) = hp;
                    *(uint32_t*)(dl + idx) = lp;
                }
            }
        }
    }
}
static constexpr int SMEM_GEMM = 2 * STAGEH * 2;  // 81920 B

// ---------------------------------------------------------------------------
// Flash attention on HMMA, m=32 per warp (halves per-SM ldmatrix traffic).
// 128-thread CTAs (4 warps x 32 q rows), 2 CTAs/SM, 3-stage KV ring,
// fixed-reference softmax, 32-key groups with ping-pong bias buffers.
// ---------------------------------------------------------------------------
__global__ __launch_bounds__(128, 2) void flash_mma_kernel(
    const __nv_bfloat16* __restrict__ Qh, const __nv_bfloat16* __restrict__ Ql,
    const __nv_bfloat16* __restrict__ Kh, const __nv_bfloat16* __restrict__ Kl,
    const __nv_bfloat16* __restrict__ Vh, const __nv_bfloat16* __restrict__ Vl,
    const float* __restrict__ bias,
    __nv_bfloat16* __restrict__ AOh, __nv_bfloat16* __restrict__ AOl)
{
    extern __shared__ char smc[];
    const uint32_t sb = smem_u32(smc);
    const int tid = threadIdx.x, wid = tid >> 5, lane = tid & 31;
    const int b = blockIdx.x, h = blockIdx.y, q0 = blockIdx.z * 128;
    const int warp_m = wid * 32;
    const size_t bh = ((size_t)b * HH + h) * SS;

    // Q fragments for two m16 tiles (reused over all key tiles)
    uint32_t qfh[2][4][4], qfl[2][4][4];
#pragma unroll
    for (int i = 0; i < 2; i++) {
        size_t rA = (bh + q0 + warp_m + i * 16 + (lane >> 2)) * HD;
        size_t rB = rA + 8 * HD;
        int c0 = 2 * (lane & 3);
#pragma unroll
        for (int t = 0; t < 4; t++) {
            qfh[i][t][0] = *(const uint32_t*)(Qh + rA + 16 * t + c0);
            qfh[i][t][1] = *(const uint32_t*)(Qh + rB + 16 * t + c0);
            qfh[i][t][2] = *(const uint32_t*)(Qh + rA + 16 * t + 8 + c0);
            qfh[i][t][3] = *(const uint32_t*)(Qh + rB + 16 * t + 8 + c0);
            qfl[i][t][0] = *(const uint32_t*)(Ql + rA + 16 * t + c0);
            qfl[i][t][1] = *(const uint32_t*)(Ql + rB + 16 * t + c0);
            qfl[i][t][2] = *(const uint32_t*)(Ql + rA + 16 * t + 8 + c0);
            qfl[i][t][3] = *(const uint32_t*)(Ql + rB + 16 * t + 8 + c0);
        }
    }

    // bias row pointers per m-tile
    const float* bp0[2];
    const float* bp1[2];
#pragma unroll
    for (int i = 0; i < 2; i++) {
        bp0[i] = bias + ((size_t)h * SS + q0 + warp_m + i * 16 + (lane >> 2)) * SS
                 + 2 * (lane & 3);
        bp1[i] = bp0[i] + 8 * SS;
    }

    float O[2][8][4];
#pragma unroll
    for (int i = 0; i < 2; i++)
#pragma unroll
        for (int j = 0; j < 8; j++)
#pragma unroll
            for (int r = 0; r < 4; r++) O[i][j][r] = 0.f;
    float lA[2] = {0.f, 0.f}, lB[2] = {0.f, 0.f};

    // s[g][i][j][r]: group g (32 keys = 4 n8), m-tile i. Doubles as bias buf.
    float s[2][2][4][4];
#pragma unroll
    for (int g = 0; g < 2; g++)
#pragma unroll
        for (int i = 0; i < 2; i++)
#pragma unroll
            for (int j = 0; j < 4; j++) {
                float2 b0 = *(const float2*)(bp0[i] + g * 32 + 8 * j);
                float2 b1 = *(const float2*)(bp1[i] + g * 32 + 8 * j);
                s[g][i][j][0] = b0.x; s[g][i][j][1] = b0.y;
                s[g][i][j][2] = b1.x; s[g][i][j][3] = b1.y;
            }

    auto load_stage = [&](int kt) {
        if (kt < NFT) {
            uint32_t base = sb + (kt % 3) * FKVB;
            int k0 = kt * 64;
#pragma unroll
            for (int t = 0; t < 16; t++) {
                int c = tid + t * 128;                   // 0..2047
                int mat = c >> 9;
                int idx = c & 511;
                int row = idx >> 3, ch = idx & 7;
                const __nv_bfloat16* src = (mat == 0) ? Kh : (mat == 1) ? Kl
                                         : (mat == 2) ? Vh : Vl;
                cp_async16(base + mat * FMATB + (uint32_t)(row * FROWH + ch * 8) * 2,
                           src + (bh + k0 + row) * HD + ch * 8);
            }
        }
        asm volatile("cp.async.commit_group;" ::: "memory");
    };

    load_stage(0);
    load_stage(1);

    const int krow = ((lane >> 4) & 1) * 8 + (lane & 7);
    const int kcol = ((lane >> 3) & 1) * 8;
    const int vrow = ((lane >> 3) & 1) * 8 + (lane & 7);
    const int vcol = ((lane >> 4) & 1) * 8;

    for (int kt = 0; kt < NFT; kt++) {
        __syncthreads();                  // all warps done with stage (kt-1)%3
        load_stage(kt + 2);
        asm volatile("cp.async.wait_group 2;" ::: "memory");  // stage kt ready

        const uint32_t kvb = sb + (kt % 3) * FKVB;

#pragma unroll
        for (int g = 0; g < 2; g++) {          // 32-key groups
            // ---- QK: K frags shared across both m-tiles (3-term) ----
#pragma unroll
            for (int dt = 0; dt < 4; dt++) {
#pragma unroll
                for (int c = 0; c < 2; c++) {
                    uint32_t addr = kvb + (uint32_t)((g * 32 + c * 16 + krow) * FROWH
                                                     + 16 * dt + kcol) * 2;
                    uint32_t k4h[4], k4l[4];
                    ldmx4(k4h, addr);
                    ldmx4(k4l, addr + FMATB);
#pragma unroll
                    for (int i = 0; i < 2; i++) {
                        float* s0 = s[g][i][2 * c];
                        float* s1 = s[g][i][2 * c + 1];
                        mma_bf16(s0, qfh[i][dt], k4h);
                        mma_bf16(s1, qfh[i][dt], k4h + 2);
                        mma_bf16(s0, qfh[i][dt], k4l);
                        mma_bf16(s1, qfh[i][dt], k4l + 2);
                        mma_bf16(s0, qfl[i][dt], k4h);
                        mma_bf16(s1, qfl[i][dt], k4h + 2);
                    }
                }
            }

            // ---- exp + per-thread partial row sums ----
#pragma unroll
            for (int i = 0; i < 2; i++)
#pragma unroll
                for (int j = 0; j < 4; j++) {
                    s[g][i][j][0] = __expf(s[g][i][j][0]);
                    s[g][i][j][1] = __expf(s[g][i][j][1]);
                    s[g][i][j][2] = __expf(s[g][i][j][2]);
                    s[g][i][j][3] = __expf(s[g][i][j][3]);
                    lA[i] += s[g][i][j][0] + s[g][i][j][1];
                    lB[i] += s[g][i][j][2] + s[g][i][j][3];
                }

            // ---- PV per 16-key chunk: V frags shared across m-tiles ----
#pragma unroll
            for (int c = 0; c < 2; c++) {
                uint32_t pfh[2][4], pfl[2][4];
#pragma unroll
                for (int i = 0; i < 2; i++) {
                    split2(s[g][i][2*c][0],   s[g][i][2*c][1],   pfh[i][0], pfl[i][0]);
                    split2(s[g][i][2*c][2],   s[g][i][2*c][3],   pfh[i][1], pfl[i][1]);
                    split2(s[g][i][2*c+1][0], s[g][i][2*c+1][1], pfh[i][2], pfl[i][2]);
                    split2(s[g][i][2*c+1][2], s[g][i][2*c+1][3], pfh[i][3], pfl[i][3]);
                }
#pragma unroll
                for (int jp = 0; jp < 4; jp++) {
                    uint32_t addr = kvb + 2 * FMATB
                        + (uint32_t)((g * 32 + c * 16 + vrow) * FROWH
                                     + 16 * jp + vcol) * 2;
                    uint32_t v4h[4], v4l[4];
                    ldmx4t(v4h, addr);
                    ldmx4t(v4l, addr + FMATB);
#pragma unroll
                    for (int i = 0; i < 2; i++) {
                        mma_bf16(O[i][2 * jp],     pfh[i], v4h);
                        mma_bf16(O[i][2 * jp + 1], pfh[i], v4h + 2);
                        mma_bf16(O[i][2 * jp],     pfh[i], v4l);
                        mma_bf16(O[i][2 * jp + 1], pfh[i], v4l + 2);
                        mma_bf16(O[i][2 * jp],     pfl[i], v4h);
                        mma_bf16(O[i][2 * jp + 1], pfl[i], v4h + 2);
                    }
                }
            }

            // ---- s[g] dead: prefetch bias for (kt+1, g); ~1.5 groups of
            //      MMA + barrier + cp.wait cover the LDG latency ----
            if (kt + 1 < NFT) {
                const int kn = (kt + 1) * 64 + g * 32;
#pragma unroll
                for (int i = 0; i < 2; i++)
#pragma unroll
                    for (int j = 0; j < 4; j++) {
                        float2 b0 = *(const float2*)(bp0[i] + kn + 8 * j);
                        float2 b1 = *(const float2*)(bp1[i] + kn + 8 * j);
                        s[g][i][j][0] = b0.x; s[g][i][j][1] = b0.y;
                        s[g][i][j][2] = b1.x; s[g][i][j][3] = b1.y;
                    }
            }
        }
    }

    // ---- final row-sum reduction (once) ----
#pragma unroll
    for (int i = 0; i < 2; i++) {
        lA[i] += __shfl_xor_sync(0xffffffffu, lA[i], 1);
        lA[i] += __shfl_xor_sync(0xffffffffu, lA[i], 2);
        lB[i] += __shfl_xor_sync(0xffffffffu, lB[i], 1);
        lB[i] += __shfl_xor_sync(0xffffffffu, lB[i], 2);
    }

    // ---- epilogue: normalize, split hi/lo, write out-proj A buffers ----
#pragma unroll
    for (int i = 0; i < 2; i++) {
        float iA = 1.f / lA[i], iB = 1.f / lB[i];
        size_t oA = ((size_t)b * SS + q0 + warp_m + i * 16 + (lane >> 2)) * DD
                    + h * HD;
        size_t oB = oA + 8 * DD;
#pragma unroll
        for (int j = 0; j < 8; j++) {
            int d = 8 * j + 2 * (lane & 3);
            uint32_t hp, lp;
            split2(O[i][j][0] * iA, O[i][j][1] * iA, hp, lp);
            *(uint32_t*)(AOh + oA + d) = hp;
            *(uint32_t*)(AOl + oA + d) = lp;
            split2(O[i][j][2] * iB, O[i][j][3] * iB, hp, lp);
            *(uint32_t*)(AOh + oB + d) = hp;
            *(uint32_t*)(AOl + oB + d) = lp;
        }
    }
}

// ---------------------------------------------------------------------------
extern "C" void kernel_launch(void* const* d_in, const int* in_sizes, int n_in,
                              void* d_out, int out_size)
{
    (void)in_sizes; (void)n_in; (void)out_size;
    const float* x         = (const float*)d_in[0];
    const float* attn_bias = (const float*)d_in[1];
    const float* qkv_w     = (const float*)d_in[2];
    const float* qkv_b     = (const float*)d_in[3];
    const float* out_w     = (const float*)d_in[4];
    const float* out_b     = (const float*)d_in[5];
    float* out = (float*)d_out;

    __nv_bfloat16 *ahi, *alo, *whi, *wlo, *qh, *ql, *kh, *kl, *vh, *vl;
    cudaGetSymbolAddress((void**)&ahi, g_ahi);
    cudaGetSymbolAddress((void**)&alo, g_alo);
    cudaGetSymbolAddress((void**)&whi, g_whi);
    cudaGetSymbolAddress((void**)&wlo, g_wlo);
    cudaGetSymbolAddress((void**)&qh,  g_qh);
    cudaGetSymbolAddress((void**)&ql,  g_ql);
    cudaGetSymbolAddress((void**)&kh,  g_kh);
    cudaGetSymbolAddress((void**)&kl,  g_kl);
    cudaGetSymbolAddress((void**)&vh,  g_vh);
    cudaGetSymbolAddress((void**)&vl,  g_vl);

    cudaFuncSetAttribute(gemm_mma_kernel,
                         cudaFuncAttributeMaxDynamicSharedMemorySize, SMEM_GEMM);
    cudaFuncSetAttribute(flash_mma_kernel,
                         cudaFuncAttributeMaxDynamicSharedMemorySize, FLASH_SMEM);

    // 1) split x and qkv_w into bf16 hi/lo
    {
        int n4 = MM * GK / 4;
        convert_kernel<<<(n4 + 255) / 256, 256>>>(x, ahi, alo, n4);
        int w4 = DQKV * GK / 4;
        convert_kernel<<<(w4 + 255) / 256, 256>>>(qkv_w, whi, wlo, w4);
    }
    // 2) QKV projection; epilogue emits q/k/v hi-lo bf16 in [b,h,s,d]
    gemm_mma_kernel<<<dim3(DQKV / BN, MM / BM), 256, SMEM_GEMM>>>(
        ahi, alo, whi, wlo, qkv_b, out /*unused*/, DQKV, 1);

    // 3) Flash attention on tensor cores -> ahi/alo ([b*s][d] hi/lo)
    flash_mma_kernel<<<dim3(BB, HH, SS / 128), 128, FLASH_SMEM>>>(
        qh, ql, kh, kl, vh, vl, attn_bias, ahi, alo);

    // 4) split out_w
    {
        int w4 = DD * DD / 4;
        convert_kernel<<<(w4 + 255) / 256, 256>>>(out_w, whi, wlo, w4);
    }
    // 5) Output projection -> d_out
    gemm_mma_kernel<<<dim3(DD / BN, MM / BM), 256, SMEM_GEMM>>>(
        ahi, alo, whi, wlo, out_b, out, DD, 0);
}

// round 9
// speedup vs baseline: 1.0220x; 1.0008x over previous
#include <cuda_runtime.h>
#include <cuda_bf16.h>
#include <cstdint>
#include <math.h>

// Problem constants
#define BB   4
#define SS   2048
#define DD   1024
#define HH   16
#define HD   64
#define DQKV 3072
#define MM   (BB*SS)          // 8192
#define GK   1024

// GEMM tiling
#define BM 128
#define BN 128
#define BK 32
#define NKT (GK/BK)           // 32
#define ROWH 40               // padded row stride in halfs (80B)
#define MATH (BM*ROWH)
#define STAGEH (4*MATH)

// Flash smem layout: 3-stage KV ring (Khi,Klo,Vhi,Vlo per stage)
#define FROWH 72                      // K/V row stride in halfs (144B)
#define FMATB (64*FROWH*2)            // 9216 B per 64x64 bf16 matrix
#define FKVB  (4*FMATB)               // 36864 B per stage
#define FLASH_SMEM (3*FKVB)           // 110592 B -> 2 CTAs/SM
#define NFT (SS/64)                   // 32 key tiles

// Scratch (allocation-free: device globals)
__device__ __nv_bfloat16 g_ahi[(size_t)MM * GK];
__device__ __nv_bfloat16 g_alo[(size_t)MM * GK];
__device__ __nv_bfloat16 g_whi[(size_t)DQKV * GK];
__device__ __nv_bfloat16 g_wlo[(size_t)DQKV * GK];
__device__ __nv_bfloat16 g_qh[(size_t)MM * DD];   // [b,h,s,d]
__device__ __nv_bfloat16 g_ql[(size_t)MM * DD];
__device__ __nv_bfloat16 g_kh[(size_t)MM * DD];
__device__ __nv_bfloat16 g_kl[(size_t)MM * DD];
__device__ __nv_bfloat16 g_vh[(size_t)MM * DD];
__device__ __nv_bfloat16 g_vl[(size_t)MM * DD];

// ---------------------------------------------------------------------------
// PTX helpers (sm_80-portable: cp.async, ldmatrix, mma.sync)
// ---------------------------------------------------------------------------
__device__ __forceinline__ uint32_t smem_u32(const void* p) {
    uint32_t a;
    asm("{ .reg .u64 t; cvta.to.shared.u64 t, %1; cvt.u32.u64 %0, t; }"
        : "=r"(a) : "l"(p));
    return a;
}
__device__ __forceinline__ void cp_async16(uint32_t dst, const void* src) {
    asm volatile("cp.async.cg.shared.global [%0], [%1], 16;" :: "r"(dst), "l"(src));
}
__device__ __forceinline__ void ldmx4(uint32_t* r, uint32_t addr) {
    asm volatile("ldmatrix.sync.aligned.m8n8.x4.shared.b16 {%0,%1,%2,%3}, [%4];"
                 : "=r"(r[0]), "=r"(r[1]), "=r"(r[2]), "=r"(r[3]) : "r"(addr));
}
__device__ __forceinline__ void ldmx4t(uint32_t* r, uint32_t addr) {
    asm volatile("ldmatrix.sync.aligned.m8n8.x4.trans.shared.b16 {%0,%1,%2,%3}, [%4];"
                 : "=r"(r[0]), "=r"(r[1]), "=r"(r[2]), "=r"(r[3]) : "r"(addr));
}
// NOT volatile: pure register op; lets ptxas software-pipeline MMA chains.
__device__ __forceinline__ void mma_bf16(float* d, const uint32_t* a, const uint32_t* b) {
    asm("mma.sync.aligned.m16n8k16.row.col.f32.bf16.bf16.f32 "
        "{%0,%1,%2,%3}, {%4,%5,%6,%7}, {%8,%9}, {%0,%1,%2,%3};"
        : "+f"(d[0]), "+f"(d[1]), "+f"(d[2]), "+f"(d[3])
        : "r"(a[0]), "r"(a[1]), "r"(a[2]), "r"(a[3]), "r"(b[0]), "r"(b[1]));
}
__device__ __forceinline__ void split2(float x, float y, uint32_t& hi, uint32_t& lo) {
    __nv_bfloat16 hx = __float2bfloat16(x);
    __nv_bfloat16 hy = __float2bfloat16(y);
    __nv_bfloat16 lx = __float2bfloat16(x - __bfloat162float(hx));
    __nv_bfloat16 ly = __float2bfloat16(y - __bfloat162float(hy));
    __nv_bfloat162 H(hx, hy), L(lx, ly);
    hi = *reinterpret_cast<uint32_t*>(&H);
    lo = *reinterpret_cast<uint32_t*>(&L);
}

// ---------------------------------------------------------------------------
// fp32 -> (hi, lo) bf16 split (bulk)
// ---------------------------------------------------------------------------
__global__ __launch_bounds__(256) void convert_kernel(
    const float* __restrict__ in, __nv_bfloat16* __restrict__ hi,
    __nv_bfloat16* __restrict__ lo, int n4)
{
    int i = blockIdx.x * blockDim.x + threadIdx.x;
    if (i >= n4) return;
    float4 v = *(const float4*)(in + (size_t)i * 4);
    uint32_t h0, l0, h1, l1;
    split2(v.x, v.y, h0, l0);
    split2(v.z, v.w, h1, l1);
    uint32_t* hp = (uint32_t*)(hi + (size_t)i * 4);
    uint32_t* lp = (uint32_t*)(lo + (size_t)i * 4);
    hp[0] = h0; hp[1] = h1;
    lp[0] = l0; lp[1] = l1;
}

// ---------------------------------------------------------------------------
// HMMA GEMM: C = A @ W^T + bias. mode 0: fp32 C. mode 1: QKV epilogue ->
// write q(*0.125)/k/v as hi/lo bf16 in [b,h,s,d] layout to device globals.
// ---------------------------------------------------------------------------
__global__ __launch_bounds__(256, 2) void gemm_mma_kernel(
    const __nv_bfloat16* __restrict__ Ahi, const __nv_bfloat16* __restrict__ Alo,
    const __nv_bfloat16* __restrict__ Whi, const __nv_bfloat16* __restrict__ Wlo,
    const float* __restrict__ bias, float* __restrict__ C, int N, int mode)
{
    extern __shared__ __nv_bfloat16 smg[];
    const uint32_t sb = smem_u32(smg);
    const int tid  = threadIdx.x;
    const int wid  = tid >> 5;
    const int lane = tid & 31;
    const int m0 = blockIdx.y * BM;
    const int n0 = blockIdx.x * BN;
    const int warp_m = (wid >> 2) * 64;
    const int warp_n = (wid & 3) * 32;

    float acc[4][4][4];
#pragma unroll
    for (int i = 0; i < 4; i++)
#pragma unroll
        for (int j = 0; j < 4; j++)
#pragma unroll
            for (int r = 0; r < 4; r++) acc[i][j][r] = 0.f;

    const __nv_bfloat16* gsrc[4] = {Ahi, Alo, Whi, Wlo};

    auto load_stage = [&](int kt, int st) {
        const int kcol = kt * BK;
#pragma unroll
        for (int t = 0; t < 8; t++) {
            int c   = tid + t * 256;
            int mat = c >> 9;
            int idx = c & 511;
            int row = idx >> 2;
            int c16 = idx & 3;
            int grow = (mat < 2 ? m0 : n0) + row;
            const __nv_bfloat16* src = gsrc[mat] + (size_t)grow * GK + kcol + c16 * 8;
            uint32_t dst = sb + (uint32_t)(st * STAGEH + mat * MATH + row * ROWH + c16 * 8) * 2;
            cp_async16(dst, src);
        }
        asm volatile("cp.async.commit_group;" ::: "memory");
    };

    load_stage(0, 0);

    for (int kt = 0; kt < NKT; kt++) {
        const int st = kt & 1;
        if (kt + 1 < NKT) {
            load_stage(kt + 1, st ^ 1);
            asm volatile("cp.async.wait_group 1;" ::: "memory");
        } else {
            asm volatile("cp.async.wait_group 0;" ::: "memory");
        }
        __syncthreads();

        const uint32_t stb = sb + (uint32_t)(st * STAGEH) * 2;
        const uint32_t aHi = stb;
        const uint32_t aLo = stb + MATH * 2;
        const uint32_t wHi = stb + 2 * MATH * 2;
        const uint32_t wLo = stb + 3 * MATH * 2;

#pragma unroll
        for (int ks = 0; ks < 2; ks++) {
            const int kk = ks * 16;
            uint32_t ah[4][4], al[4][4], bh[4][2], bl[4][2];
#pragma unroll
            for (int i = 0; i < 4; i++) {
                uint32_t off = (uint32_t)((warp_m + i * 16 + (lane & 15)) * ROWH
                                          + kk + (lane >> 4) * 8) * 2;
                ldmx4(ah[i], aHi + off);
                ldmx4(al[i], aLo + off);
            }
#pragma unroll
            for (int jp2 = 0; jp2 < 2; jp2++) {
                int g = lane >> 3;
                uint32_t off = (uint32_t)((warp_n + (2 * jp2 + (g >> 1)) * 8
                                           + (lane & 7)) * ROWH
                                          + kk + (g & 1) * 8) * 2;
                uint32_t r4[4];
                ldmx4(r4, wHi + off);
                bh[2 * jp2][0] = r4[0]; bh[2 * jp2][1] = r4[1];
                bh[2 * jp2 + 1][0] = r4[2]; bh[2 * jp2 + 1][1] = r4[3];
                ldmx4(r4, wLo + off);
                bl[2 * jp2][0] = r4[0]; bl[2 * jp2][1] = r4[1];
                bl[2 * jp2 + 1][0] = r4[2]; bl[2 * jp2 + 1][1] = r4[3];
            }
#pragma unroll
            for (int i = 0; i < 4; i++)
#pragma unroll
                for (int j = 0; j < 4; j++) mma_bf16(acc[i][j], ah[i], bh[j]);
#pragma unroll
            for (int i = 0; i < 4; i++)
#pragma unroll
                for (int j = 0; j < 4; j++) mma_bf16(acc[i][j], ah[i], bl[j]);
#pragma unroll
            for (int i = 0; i < 4; i++)
#pragma unroll
                for (int j = 0; j < 4; j++) mma_bf16(acc[i][j], al[i], bh[j]);
        }
        __syncthreads();
    }

    if (mode == 0) {
#pragma unroll
        for (int i = 0; i < 4; i++) {
#pragma unroll
            for (int j = 0; j < 4; j++) {
                int m = m0 + warp_m + i * 16 + (lane >> 2);
                int n = n0 + warp_n + j * 8 + (lane & 3) * 2;
                float2 bv = *(const float2*)(bias + n);
                float2 o0 = { acc[i][j][0] + bv.x, acc[i][j][1] + bv.y };
                float2 o1 = { acc[i][j][2] + bv.x, acc[i][j][3] + bv.y };
                *(float2*)(C + (size_t)m * N + n) = o0;
                *(float2*)(C + (size_t)(m + 8) * N + n) = o1;
            }
        }
    } else {
#pragma unroll
        for (int i = 0; i < 4; i++) {
#pragma unroll
            for (int j = 0; j < 4; j++) {
                int m = m0 + warp_m + i * 16 + (lane >> 2);
                int n = n0 + warp_n + j * 8 + (lane & 3) * 2;
                float2 bv = *(const float2*)(bias + n);
                int sel = n >> 10;
                int hh  = (n & 1023) >> 6;
                int d   = n & 63;
                float sc = (sel == 0) ? 0.125f : 1.0f;
                __nv_bfloat16 *dh, *dl;
                if (sel == 0)      { dh = g_qh; dl = g_ql; }
                else if (sel == 1) { dh = g_kh; dl = g_kl; }
                else               { dh = g_vh; dl = g_vl; }
#pragma unroll
                for (int rr = 0; rr < 2; rr++) {
                    int mm = m + rr * 8;
                    float vx = (acc[i][j][rr * 2 + 0] + bv.x) * sc;
                    float vy = (acc[i][j][rr * 2 + 1] + bv.y) * sc;
                    uint32_t hp, lp;
                    split2(vx, vy, hp, lp);
                    size_t idx = (((size_t)(mm >> 11) * HH + hh) * SS + (mm & 2047)) * HD + d;
                    *(uint32_t*)(dh + idx) = hp;
                    *(uint32_t*)(dl + idx) = lp;
                }
            }
        }
    }
}
static constexpr int SMEM_GEMM = 2 * STAGEH * 2;  // 81920 B

// ---------------------------------------------------------------------------
// Flash attention on HMMA, m=32 per warp, non-volatile MMAs (ptxas pipelines
// them) + term-major chain ordering. 128-thread CTAs, 2 CTAs/SM, 3-stage ring.
// ---------------------------------------------------------------------------
__global__ __launch_bounds__(128, 2) void flash_mma_kernel(
    const __nv_bfloat16* __restrict__ Qh, const __nv_bfloat16* __restrict__ Ql,
    const __nv_bfloat16* __restrict__ Kh, const __nv_bfloat16* __restrict__ Kl,
    const __nv_bfloat16* __restrict__ Vh, const __nv_bfloat16* __restrict__ Vl,
    const float* __restrict__ bias,
    __nv_bfloat16* __restrict__ AOh, __nv_bfloat16* __restrict__ AOl)
{
    extern __shared__ char smc[];
    const uint32_t sb = smem_u32(smc);
    const int tid = threadIdx.x, wid = tid >> 5, lane = tid & 31;
    const int b = blockIdx.x, h = blockIdx.y, q0 = blockIdx.z * 128;
    const int warp_m = wid * 32;
    const size_t bh = ((size_t)b * HH + h) * SS;

    // Q fragments for two m16 tiles (reused over all key tiles)
    uint32_t qfh[2][4][4], qfl[2][4][4];
#pragma unroll
    for (int i = 0; i < 2; i++) {
        size_t rA = (bh + q0 + warp_m + i * 16 + (lane >> 2)) * HD;
        size_t rB = rA + 8 * HD;
        int c0 = 2 * (lane & 3);
#pragma unroll
        for (int t = 0; t < 4; t++) {
            qfh[i][t][0] = *(const uint32_t*)(Qh + rA + 16 * t + c0);
            qfh[i][t][1] = *(const uint32_t*)(Qh + rB + 16 * t + c0);
            qfh[i][t][2] = *(const uint32_t*)(Qh + rA + 16 * t + 8 + c0);
            qfh[i][t][3] = *(const uint32_t*)(Qh + rB + 16 * t + 8 + c0);
            qfl[i][t][0] = *(const uint32_t*)(Ql + rA + 16 * t + c0);
            qfl[i][t][1] = *(const uint32_t*)(Ql + rB + 16 * t + c0);
            qfl[i][t][2] = *(const uint32_t*)(Ql + rA + 16 * t + 8 + c0);
            qfl[i][t][3] = *(const uint32_t*)(Ql + rB + 16 * t + 8 + c0);
        }
    }

    // bias row pointers per m-tile
    const float* bp0[2];
    const float* bp1[2];
#pragma unroll
    for (int i = 0; i < 2; i++) {
        bp0[i] = bias + ((size_t)h * SS + q0 + warp_m + i * 16 + (lane >> 2)) * SS
                 + 2 * (lane & 3);
        bp1[i] = bp0[i] + 8 * SS;
    }

    float O[2][8][4];
#pragma unroll
    for (int i = 0; i < 2; i++)
#pragma unroll
        for (int j = 0; j < 8; j++)
#pragma unroll
            for (int r = 0; r < 4; r++) O[i][j][r] = 0.f;
    float lA[2] = {0.f, 0.f}, lB[2] = {0.f, 0.f};

    // s[g][i][j][r]: group g (32 keys = 4 n8), m-tile i. Doubles as bias buf.
    float s[2][2][4][4];
#pragma unroll
    for (int g = 0; g < 2; g++)
#pragma unroll
        for (int i = 0; i < 2; i++)
#pragma unroll
            for (int j = 0; j < 4; j++) {
                float2 b0 = *(const float2*)(bp0[i] + g * 32 + 8 * j);
                float2 b1 = *(const float2*)(bp1[i] + g * 32 + 8 * j);
                s[g][i][j][0] = b0.x; s[g][i][j][1] = b0.y;
                s[g][i][j][2] = b1.x; s[g][i][j][3] = b1.y;
            }

    auto load_stage = [&](int kt) {
        if (kt < NFT) {
            uint32_t base = sb + (kt % 3) * FKVB;
            int k0 = kt * 64;
#pragma unroll
            for (int t = 0; t < 16; t++) {
                int c = tid + t * 128;                   // 0..2047
                int mat = c >> 9;
                int idx = c & 511;
                int row = idx >> 3, ch = idx & 7;
                const __nv_bfloat16* src = (mat == 0) ? Kh : (mat == 1) ? Kl
                                         : (mat == 2) ? Vh : Vl;
                cp_async16(base + mat * FMATB + (uint32_t)(row * FROWH + ch * 8) * 2,
                           src + (bh + k0 + row) * HD + ch * 8);
            }
        }
        asm volatile("cp.async.commit_group;" ::: "memory");
    };

    load_stage(0);
    load_stage(1);

    const int krow = ((lane >> 4) & 1) * 8 + (lane & 7);
    const int kcol = ((lane >> 3) & 1) * 8;
    const int vrow = ((lane >> 3) & 1) * 8 + (lane & 7);
    const int vcol = ((lane >> 4) & 1) * 8;

    for (int kt = 0; kt < NFT; kt++) {
        __syncthreads();                  // all warps done with stage (kt-1)%3
        load_stage(kt + 2);
        asm volatile("cp.async.wait_group 2;" ::: "memory");  // stage kt ready

        const uint32_t kvb = sb + (kt % 3) * FKVB;

#pragma unroll
        for (int g = 0; g < 2; g++) {          // 32-key groups
            // ---- QK: K frags shared across both m-tiles; term-major so each
            //      accumulator's dependent MMAs are spaced by 4+ ----
#pragma unroll
            for (int dt = 0; dt < 4; dt++) {
#pragma unroll
                for (int c = 0; c < 2; c++) {
                    uint32_t addr = kvb + (uint32_t)((g * 32 + c * 16 + krow) * FROWH
                                                     + 16 * dt + kcol) * 2;
                    uint32_t k4h[4], k4l[4];
                    ldmx4(k4h, addr);
                    ldmx4(k4l, addr + FMATB);
                    // term hh (4 independent accumulators)
                    mma_bf16(s[g][0][2*c],   qfh[0][dt], k4h);
                    mma_bf16(s[g][0][2*c+1], qfh[0][dt], k4h + 2);
                    mma_bf16(s[g][1][2*c],   qfh[1][dt], k4h);
                    mma_bf16(s[g][1][2*c+1], qfh[1][dt], k4h + 2);
                    // term hl
                    mma_bf16(s[g][0][2*c],   qfh[0][dt], k4l);
                    mma_bf16(s[g][0][2*c+1], qfh[0][dt], k4l + 2);
                    mma_bf16(s[g][1][2*c],   qfh[1][dt], k4l);
                    mma_bf16(s[g][1][2*c+1], qfh[1][dt], k4l + 2);
                    // term lh
                    mma_bf16(s[g][0][2*c],   qfl[0][dt], k4h);
                    mma_bf16(s[g][0][2*c+1], qfl[0][dt], k4h + 2);
                    mma_bf16(s[g][1][2*c],   qfl[1][dt], k4h);
                    mma_bf16(s[g][1][2*c+1], qfl[1][dt], k4h + 2);
                }
            }

            // ---- exp + per-thread partial row sums ----
#pragma unroll
            for (int i = 0; i < 2; i++)
#pragma unroll
                for (int j = 0; j < 4; j++) {
                    s[g][i][j][0] = __expf(s[g][i][j][0]);
                    s[g][i][j][1] = __expf(s[g][i][j][1]);
                    s[g][i][j][2] = __expf(s[g][i][j][2]);
                    s[g][i][j][3] = __expf(s[g][i][j][3]);
                    lA[i] += s[g][i][j][0] + s[g][i][j][1];
                    lB[i] += s[g][i][j][2] + s[g][i][j][3];
                }

            // ---- PV per 16-key chunk; term-major (4 indep accums/term) ----
#pragma unroll
            for (int c = 0; c < 2; c++) {
                uint32_t pfh[2][4], pfl[2][4];
#pragma unroll
                for (int i = 0; i < 2; i++) {
                    split2(s[g][i][2*c][0],   s[g][i][2*c][1],   pfh[i][0], pfl[i][0]);
                    split2(s[g][i][2*c][2],   s[g][i][2*c][3],   pfh[i][1], pfl[i][1]);
                    split2(s[g][i][2*c+1][0], s[g][i][2*c+1][1], pfh[i][2], pfl[i][2]);
                    split2(s[g][i][2*c+1][2], s[g][i][2*c+1][3], pfh[i][3], pfl[i][3]);
                }
#pragma unroll
                for (int jp = 0; jp < 4; jp++) {
                    uint32_t addr = kvb + 2 * FMATB
                        + (uint32_t)((g * 32 + c * 16 + vrow) * FROWH
                                     + 16 * jp + vcol) * 2;
                    uint32_t v4h[4], v4l[4];
                    ldmx4t(v4h, addr);
                    ldmx4t(v4l, addr + FMATB);
                    // term pfh*vh
                    mma_bf16(O[0][2*jp],   pfh[0], v4h);
                    mma_bf16(O[0][2*jp+1], pfh[0], v4h + 2);
                    mma_bf16(O[1][2*jp],   pfh[1], v4h);
                    mma_bf16(O[1][2*jp+1], pfh[1], v4h + 2);
                    // term pfh*vl
                    mma_bf16(O[0][2*jp],   pfh[0], v4l);
                    mma_bf16(O[0][2*jp+1], pfh[0], v4l + 2);
                    mma_bf16(O[1][2*jp],   pfh[1], v4l);
                    mma_bf16(O[1][2*jp+1], pfh[1], v4l + 2);
                    // term pfl*vh
                    mma_bf16(O[0][2*jp],   pfl[0], v4h);
                    mma_bf16(O[0][2*jp+1], pfl[0], v4h + 2);
                    mma_bf16(O[1][2*jp],   pfl[1], v4h);
                    mma_bf16(O[1][2*jp+1], pfl[1], v4h + 2);
                }
            }

            // ---- s[g] dead: prefetch bias for (kt+1, g) ----
            if (kt + 1 < NFT) {
                const int kn = (kt + 1) * 64 + g * 32;
#pragma unroll
                for (int i = 0; i < 2; i++)
#pragma unroll
                    for (int j = 0; j < 4; j++) {
                        float2 b0 = *(const float2*)(bp0[i] + kn + 8 * j);
                        float2 b1 = *(const float2*)(bp1[i] + kn + 8 * j);
                        s[g][i][j][0] = b0.x; s[g][i][j][1] = b0.y;
                        s[g][i][j][2] = b1.x; s[g][i][j][3] = b1.y;
                    }
            }
        }
    }

    // ---- final row-sum reduction (once) ----
#pragma unroll
    for (int i = 0; i < 2; i++) {
        lA[i] += __shfl_xor_sync(0xffffffffu, lA[i], 1);
        lA[i] += __shfl_xor_sync(0xffffffffu, lA[i], 2);
        lB[i] += __shfl_xor_sync(0xffffffffu, lB[i], 1);
        lB[i] += __shfl_xor_sync(0xffffffffu, lB[i], 2);
    }

    // ---- epilogue: normalize, split hi/lo, write out-proj A buffers ----
#pragma unroll
    for (int i = 0; i < 2; i++) {
        float iA = 1.f / lA[i], iB = 1.f / lB[i];
        size_t oA = ((size_t)b * SS + q0 + warp_m + i * 16 + (lane >> 2)) * DD
                    + h * HD;
        size_t oB = oA + 8 * DD;
#pragma unroll
        for (int j = 0; j < 8; j++) {
            int d = 8 * j + 2 * (lane & 3);
            uint32_t hp, lp;
            split2(O[i][j][0] * iA, O[i][j][1] * iA, hp, lp);
            *(uint32_t*)(AOh + oA + d) = hp;
            *(uint32_t*)(AOl + oA + d) = lp;
            split2(O[i][j][2] * iB, O[i][j][3] * iB, hp, lp);
            *(uint32_t*)(AOh + oB + d) = hp;
            *(uint32_t*)(AOl + oB + d) = lp;
        }
    }
}

// ---------------------------------------------------------------------------
extern "C" void kernel_launch(void* const* d_in, const int* in_sizes, int n_in,
                              void* d_out, int out_size)
{
    (void)in_sizes; (void)n_in; (void)out_size;
    const float* x         = (const float*)d_in[0];
    const float* attn_bias = (const float*)d_in[1];
    const float* qkv_w     = (const float*)d_in[2];
    const float* qkv_b     = (const float*)d_in[3];
    const float* out_w     = (const float*)d_in[4];
    const float* out_b     = (const float*)d_in[5];
    float* out = (float*)d_out;

    __nv_bfloat16 *ahi, *alo, *whi, *wlo, *qh, *ql, *kh, *kl, *vh, *vl;
    cudaGetSymbolAddress((void**)&ahi, g_ahi);
    cudaGetSymbolAddress((void**)&alo, g_alo);
    cudaGetSymbolAddress((void**)&whi, g_whi);
    cudaGetSymbolAddress((void**)&wlo, g_wlo);
    cudaGetSymbolAddress((void**)&qh,  g_qh);
    cudaGetSymbolAddress((void**)&ql,  g_ql);
    cudaGetSymbolAddress((void**)&kh,  g_kh);
    cudaGetSymbolAddress((void**)&kl,  g_kl);
    cudaGetSymbolAddress((void**)&vh,  g_vh);
    cudaGetSymbolAddress((void**)&vl,  g_vl);

    cudaFuncSetAttribute(gemm_mma_kernel,
                         cudaFuncAttributeMaxDynamicSharedMemorySize, SMEM_GEMM);
    cudaFuncSetAttribute(flash_mma_kernel,
                         cudaFuncAttributeMaxDynamicSharedMemorySize, FLASH_SMEM);

    // 1) split x and qkv_w into bf16 hi/lo
    {
        int n4 = MM * GK / 4;
        convert_kernel<<<(n4 + 255) / 256, 256>>>(x, ahi, alo, n4);
        int w4 = DQKV * GK / 4;
        convert_kernel<<<(w4 + 255) / 256, 256>>>(qkv_w, whi, wlo, w4);
    }
    // 2) QKV projection; epilogue emits q/k/v hi-lo bf16 in [b,h,s,d]
    gemm_mma_kernel<<<dim3(DQKV / BN, MM / BM), 256, SMEM_GEMM>>>(
        ahi, alo, whi, wlo, qkv_b, out /*unused*/, DQKV, 1);

    // 3) Flash attention on tensor cores -> ahi/alo ([b*s][d] hi/lo)
    flash_mma_kernel<<<dim3(BB, HH, SS / 128), 128, FLASH_SMEM>>>(
        qh, ql, kh, kl, vh, vl, attn_bias, ahi, alo);

    // 4) split out_w
    {
        int w4 = DD * DD / 4;
        convert_kernel<<<(w4 + 255) / 256, 256>>>(out_w, whi, wlo, w4);
    }
    // 5) Output projection -> d_out
    gemm_mma_kernel<<<dim3(DD / BN, MM / BM), 256, SMEM_GEMM>>>(
        ahi, alo, whi, wlo, out_b, out, DD, 0);
}

// round 10
// speedup vs baseline: 1.2783x; 1.2508x over previous
#include <cuda_runtime.h>
#include <cuda_bf16.h>
#include <cuda_fp16.h>
#include <cstdint>
#include <math.h>

// Problem constants
#define BB   4
#define SS   2048
#define DD   1024
#define HH   16
#define HD   64
#define DQKV 3072
#define MM   (BB*SS)          // 8192
#define GK   1024

// GEMM tiling
#define BM 128
#define BN 128
#define BK 32
#define NKT (GK/BK)           // 32
#define ROWH 40               // padded row stride in halfs (80B)
#define MATH (BM*ROWH)
#define STAGEH (4*MATH)

// Flash smem layout: 3-stage ring, single-fp16 K and V per stage
#define FROWH 72                      // K/V row stride in halfs (144B)
#define FMATB (64*FROWH*2)            // 9216 B per 64x64 fp16 matrix
#define FKVB  (2*FMATB)               // 18432 B per stage (K, V)
#define FLASH_SMEM (3*FKVB)           // 55296 B
#define NFT (SS/64)                   // 32 key tiles
#define CSUB 6.0f                     // softmax shift: p = exp(s - 6) fits fp16

// Scratch (allocation-free: device globals)
__device__ __nv_bfloat16 g_ahi[(size_t)MM * GK];
__device__ __nv_bfloat16 g_alo[(size_t)MM * GK];
__device__ __nv_bfloat16 g_whi[(size_t)DQKV * GK];
__device__ __nv_bfloat16 g_wlo[(size_t)DQKV * GK];
__device__ __half g_qf[(size_t)MM * DD];   // [b,h,s,d] fp16, q pre-scaled
__device__ __half g_kf[(size_t)MM * DD];
__device__ __half g_vf[(size_t)MM * DD];

// ---------------------------------------------------------------------------
// PTX helpers (sm_80-portable: cp.async, ldmatrix, mma.sync)
// ---------------------------------------------------------------------------
__device__ __forceinline__ uint32_t smem_u32(const void* p) {
    uint32_t a;
    asm("{ .reg .u64 t; cvta.to.shared.u64 t, %1; cvt.u32.u64 %0, t; }"
        : "=r"(a) : "l"(p));
    return a;
}
__device__ __forceinline__ void cp_async16(uint32_t dst, const void* src) {
    asm volatile("cp.async.cg.shared.global [%0], [%1], 16;" :: "r"(dst), "l"(src));
}
__device__ __forceinline__ void ldmx4(uint32_t* r, uint32_t addr) {
    asm volatile("ldmatrix.sync.aligned.m8n8.x4.shared.b16 {%0,%1,%2,%3}, [%4];"
                 : "=r"(r[0]), "=r"(r[1]), "=r"(r[2]), "=r"(r[3]) : "r"(addr));
}
__device__ __forceinline__ void ldmx4t(uint32_t* r, uint32_t addr) {
    asm volatile("ldmatrix.sync.aligned.m8n8.x4.trans.shared.b16 {%0,%1,%2,%3}, [%4];"
                 : "=r"(r[0]), "=r"(r[1]), "=r"(r[2]), "=r"(r[3]) : "r"(addr));
}
__device__ __forceinline__ void mma_bf16(float* d, const uint32_t* a, const uint32_t* b) {
    asm("mma.sync.aligned.m16n8k16.row.col.f32.bf16.bf16.f32 "
        "{%0,%1,%2,%3}, {%4,%5,%6,%7}, {%8,%9}, {%0,%1,%2,%3};"
        : "+f"(d[0]), "+f"(d[1]), "+f"(d[2]), "+f"(d[3])
        : "r"(a[0]), "r"(a[1]), "r"(a[2]), "r"(a[3]), "r"(b[0]), "r"(b[1]));
}
__device__ __forceinline__ void mma_f16(float* d, const uint32_t* a, const uint32_t* b) {
    asm("mma.sync.aligned.m16n8k16.row.col.f32.f16.f16.f32 "
        "{%0,%1,%2,%3}, {%4,%5,%6,%7}, {%8,%9}, {%0,%1,%2,%3};"
        : "+f"(d[0]), "+f"(d[1]), "+f"(d[2]), "+f"(d[3])
        : "r"(a[0]), "r"(a[1]), "r"(a[2]), "r"(a[3]), "r"(b[0]), "r"(b[1]));
}
__device__ __forceinline__ void split2(float x, float y, uint32_t& hi, uint32_t& lo) {
    __nv_bfloat16 hx = __float2bfloat16(x);
    __nv_bfloat16 hy = __float2bfloat16(y);
    __nv_bfloat16 lx = __float2bfloat16(x - __bfloat162float(hx));
    __nv_bfloat16 ly = __float2bfloat16(y - __bfloat162float(hy));
    __nv_bfloat162 H(hx, hy), L(lx, ly);
    hi = *reinterpret_cast<uint32_t*>(&H);
    lo = *reinterpret_cast<uint32_t*>(&L);
}
__device__ __forceinline__ uint32_t packh2(float x, float y) {
    __half2 h = __floats2half2_rn(x, y);   // low = x, high = y
    return *reinterpret_cast<uint32_t*>(&h);
}

// ---------------------------------------------------------------------------
// fp32 -> (hi, lo) bf16 split (bulk)
// ---------------------------------------------------------------------------
__global__ __launch_bounds__(256) void convert_kernel(
    const float* __restrict__ in, __nv_bfloat16* __restrict__ hi,
    __nv_bfloat16* __restrict__ lo, int n4)
{
    int i = blockIdx.x * blockDim.x + threadIdx.x;
    if (i >= n4) return;
    float4 v = *(const float4*)(in + (size_t)i * 4);
    uint32_t h0, l0, h1, l1;
    split2(v.x, v.y, h0, l0);
    split2(v.z, v.w, h1, l1);
    uint32_t* hp = (uint32_t*)(hi + (size_t)i * 4);
    uint32_t* lp = (uint32_t*)(lo + (size_t)i * 4);
    hp[0] = h0; hp[1] = h1;
    lp[0] = l0; lp[1] = l1;
}

// ---------------------------------------------------------------------------
// HMMA GEMM (3-term bf16): C = A @ W^T + bias. mode 0: fp32 C.
// mode 1: QKV epilogue -> q(*0.125)/k/v single fp16 in [b,h,s,d].
// ---------------------------------------------------------------------------
__global__ __launch_bounds__(256, 2) void gemm_mma_kernel(
    const __nv_bfloat16* __restrict__ Ahi, const __nv_bfloat16* __restrict__ Alo,
    const __nv_bfloat16* __restrict__ Whi, const __nv_bfloat16* __restrict__ Wlo,
    const float* __restrict__ bias, float* __restrict__ C, int N, int mode)
{
    extern __shared__ __nv_bfloat16 smg[];
    const uint32_t sb = smem_u32(smg);
    const int tid  = threadIdx.x;
    const int wid  = tid >> 5;
    const int lane = tid & 31;
    const int m0 = blockIdx.y * BM;
    const int n0 = blockIdx.x * BN;
    const int warp_m = (wid >> 2) * 64;
    const int warp_n = (wid & 3) * 32;

    float acc[4][4][4];
#pragma unroll
    for (int i = 0; i < 4; i++)
#pragma unroll
        for (int j = 0; j < 4; j++)
#pragma unroll
            for (int r = 0; r < 4; r++) acc[i][j][r] = 0.f;

    const __nv_bfloat16* gsrc[4] = {Ahi, Alo, Whi, Wlo};

    auto load_stage = [&](int kt, int st) {
        const int kcol = kt * BK;
#pragma unroll
        for (int t = 0; t < 8; t++) {
            int c   = tid + t * 256;
            int mat = c >> 9;
            int idx = c & 511;
            int row = idx >> 2;
            int c16 = idx & 3;
            int grow = (mat < 2 ? m0 : n0) + row;
            const __nv_bfloat16* src = gsrc[mat] + (size_t)grow * GK + kcol + c16 * 8;
            uint32_t dst = sb + (uint32_t)(st * STAGEH + mat * MATH + row * ROWH + c16 * 8) * 2;
            cp_async16(dst, src);
        }
        asm volatile("cp.async.commit_group;" ::: "memory");
    };

    load_stage(0, 0);

    for (int kt = 0; kt < NKT; kt++) {
        const int st = kt & 1;
        if (kt + 1 < NKT) {
            load_stage(kt + 1, st ^ 1);
            asm volatile("cp.async.wait_group 1;" ::: "memory");
        } else {
            asm volatile("cp.async.wait_group 0;" ::: "memory");
        }
        __syncthreads();

        const uint32_t stb = sb + (uint32_t)(st * STAGEH) * 2;
        const uint32_t aHi = stb;
        const uint32_t aLo = stb + MATH * 2;
        const uint32_t wHi = stb + 2 * MATH * 2;
        const uint32_t wLo = stb + 3 * MATH * 2;

#pragma unroll
        for (int ks = 0; ks < 2; ks++) {
            const int kk = ks * 16;
            uint32_t ah[4][4], al[4][4], bh[4][2], bl[4][2];
#pragma unroll
            for (int i = 0; i < 4; i++) {
                uint32_t off = (uint32_t)((warp_m + i * 16 + (lane & 15)) * ROWH
                                          + kk + (lane >> 4) * 8) * 2;
                ldmx4(ah[i], aHi + off);
                ldmx4(al[i], aLo + off);
            }
#pragma unroll
            for (int jp2 = 0; jp2 < 2; jp2++) {
                int g = lane >> 3;
                uint32_t off = (uint32_t)((warp_n + (2 * jp2 + (g >> 1)) * 8
                                           + (lane & 7)) * ROWH
                                          + kk + (g & 1) * 8) * 2;
                uint32_t r4[4];
                ldmx4(r4, wHi + off);
                bh[2 * jp2][0] = r4[0]; bh[2 * jp2][1] = r4[1];
                bh[2 * jp2 + 1][0] = r4[2]; bh[2 * jp2 + 1][1] = r4[3];
                ldmx4(r4, wLo + off);
                bl[2 * jp2][0] = r4[0]; bl[2 * jp2][1] = r4[1];
                bl[2 * jp2 + 1][0] = r4[2]; bl[2 * jp2 + 1][1] = r4[3];
            }
#pragma unroll
            for (int i = 0; i < 4; i++)
#pragma unroll
                for (int j = 0; j < 4; j++) mma_bf16(acc[i][j], ah[i], bh[j]);
#pragma unroll
            for (int i = 0; i < 4; i++)
#pragma unroll
                for (int j = 0; j < 4; j++) mma_bf16(acc[i][j], ah[i], bl[j]);
#pragma unroll
            for (int i = 0; i < 4; i++)
#pragma unroll
                for (int j = 0; j < 4; j++) mma_bf16(acc[i][j], al[i], bh[j]);
        }
        __syncthreads();
    }

    if (mode == 0) {
#pragma unroll
        for (int i = 0; i < 4; i++) {
#pragma unroll
            for (int j = 0; j < 4; j++) {
                int m = m0 + warp_m + i * 16 + (lane >> 2);
                int n = n0 + warp_n + j * 8 + (lane & 3) * 2;
                float2 bv = *(const float2*)(bias + n);
                float2 o0 = { acc[i][j][0] + bv.x, acc[i][j][1] + bv.y };
                float2 o1 = { acc[i][j][2] + bv.x, acc[i][j][3] + bv.y };
                *(float2*)(C + (size_t)m * N + n) = o0;
                *(float2*)(C + (size_t)(m + 8) * N + n) = o1;
            }
        }
    } else {
#pragma unroll
        for (int i = 0; i < 4; i++) {
#pragma unroll
            for (int j = 0; j < 4; j++) {
                int m = m0 + warp_m + i * 16 + (lane >> 2);
                int n = n0 + warp_n + j * 8 + (lane & 3) * 2;
                float2 bv = *(const float2*)(bias + n);
                int sel = n >> 10;
                int hh  = (n & 1023) >> 6;
                int d   = n & 63;
                float sc = (sel == 0) ? 0.125f : 1.0f;
                __half* dst = (sel == 0) ? g_qf : (sel == 1) ? g_kf : g_vf;
#pragma unroll
                for (int rr = 0; rr < 2; rr++) {
                    int mm = m + rr * 8;
                    float vx = (acc[i][j][rr * 2 + 0] + bv.x) * sc;
                    float vy = (acc[i][j][rr * 2 + 1] + bv.y) * sc;
                    size_t idx = (((size_t)(mm >> 11) * HH + hh) * SS + (mm & 2047)) * HD + d;
                    *(uint32_t*)(dst + idx) = packh2(vx, vy);
                }
            }
        }
    }
}
static constexpr int SMEM_GEMM = 2 * STAGEH * 2;  // 81920 B

// ---------------------------------------------------------------------------
// Flash attention: single-term fp16 HMMA for QK and PV (3x fewer MMAs).
// Fixed-reference softmax shifted by CSUB so p fits fp16 range.
// 256 thr, warp = 16 q rows, 3-stage K/V ring, bias LDG'd into accumulators.
// ---------------------------------------------------------------------------
__global__ __launch_bounds__(256, 2) void flash_mma_kernel(
    const __half* __restrict__ Qf, const __half* __restrict__ Kf,
    const __half* __restrict__ Vf, const float* __restrict__ bias,
    __nv_bfloat16* __restrict__ AOh, __nv_bfloat16* __restrict__ AOl)
{
    extern __shared__ char smc[];
    const uint32_t sb = smem_u32(smc);
    const int tid = threadIdx.x, wid = tid >> 5, lane = tid & 31;
    const int b = blockIdx.x, h = blockIdx.y, q0 = blockIdx.z * 128;
    const int warp_m = wid * 16;
    const size_t bh = ((size_t)b * HH + h) * SS;

    // Q fragments (fp16, pre-scaled), reused over all key tiles
    uint32_t qf[4][4];
    {
        size_t rA = (bh + q0 + warp_m + (lane >> 2)) * HD;
        size_t rB = rA + 8 * HD;
        int c0 = 2 * (lane & 3);
#pragma unroll
        for (int t = 0; t < 4; t++) {
            qf[t][0] = *(const uint32_t*)(Qf + rA + 16 * t + c0);
            qf[t][1] = *(const uint32_t*)(Qf + rB + 16 * t + c0);
            qf[t][2] = *(const uint32_t*)(Qf + rA + 16 * t + 8 + c0);
            qf[t][3] = *(const uint32_t*)(Qf + rB + 16 * t + 8 + c0);
        }
    }

    const float* bp0 = bias + ((size_t)h * SS + q0 + warp_m + (lane >> 2)) * SS
                       + 2 * (lane & 3);
    const float* bp1 = bp0 + 8 * SS;

    float O[8][4];
#pragma unroll
    for (int j = 0; j < 8; j++)
#pragma unroll
        for (int r = 0; r < 4; r++) O[j][r] = 0.f;
    float lA = 0.f, lB = 0.f;

    // s preloaded with (bias - CSUB)
    float s[8][4];
#pragma unroll
    for (int j = 0; j < 8; j++) {
        float2 b0 = *(const float2*)(bp0 + 8 * j);
        float2 b1 = *(const float2*)(bp1 + 8 * j);
        s[j][0] = b0.x - CSUB; s[j][1] = b0.y - CSUB;
        s[j][2] = b1.x - CSUB; s[j][3] = b1.y - CSUB;
    }

    auto load_stage = [&](int kt) {
        if (kt < NFT) {
            uint32_t base = sb + (kt % 3) * FKVB;
            int k0 = kt * 64;
#pragma unroll
            for (int t = 0; t < 4; t++) {
                int c = tid + t * 256;                   // 0..1023
                int mat = c >> 9;                        // 0=K, 1=V
                int idx = c & 511;
                int row = idx >> 3, ch = idx & 7;
                const __half* src = mat ? Vf : Kf;
                cp_async16(base + mat * FMATB + (uint32_t)(row * FROWH + ch * 8) * 2,
                           src + (bh + k0 + row) * HD + ch * 8);
            }
        }
        asm volatile("cp.async.commit_group;" ::: "memory");
    };

    load_stage(0);
    load_stage(1);

    const int krow = ((lane >> 4) & 1) * 8 + (lane & 7);
    const int kcol = ((lane >> 3) & 1) * 8;
    const int vrow = ((lane >> 3) & 1) * 8 + (lane & 7);
    const int vcol = ((lane >> 4) & 1) * 8;

    for (int kt = 0; kt < NFT; kt++) {
        __syncthreads();                  // all warps done with stage (kt-1)%3
        load_stage(kt + 2);
        asm volatile("cp.async.wait_group 2;" ::: "memory");  // stage kt ready

        const uint32_t kvb = sb + (kt % 3) * FKVB;

        // ---- S (= bias - C) += Q K^T, single fp16 term ----
#pragma unroll
        for (int t = 0; t < 4; t++) {
#pragma unroll
            for (int jp = 0; jp < 4; jp++) {
                uint32_t addr = kvb + (uint32_t)((jp * 16 + krow) * FROWH
                                                 + 16 * t + kcol) * 2;
                uint32_t k4[4];
                ldmx4(k4, addr);
                mma_f16(s[2 * jp],     qf[t], k4);
                mma_f16(s[2 * jp + 1], qf[t], k4 + 2);
            }
        }

        // ---- p = exp(s); fp32 partial row sums ----
#pragma unroll
        for (int j = 0; j < 8; j++) {
            s[j][0] = __expf(s[j][0]);
            s[j][1] = __expf(s[j][1]);
            s[j][2] = __expf(s[j][2]);
            s[j][3] = __expf(s[j][3]);
            lA += s[j][0] + s[j][1];
            lB += s[j][2] + s[j][3];
        }

        // ---- O += P V, single fp16 term; bias prefetch in last chunk ----
#pragma unroll
        for (int t = 0; t < 4; t++) {
            uint32_t pf[4];
            pf[0] = packh2(s[2 * t][0],     s[2 * t][1]);
            pf[1] = packh2(s[2 * t][2],     s[2 * t][3]);
            pf[2] = packh2(s[2 * t + 1][0], s[2 * t + 1][1]);
            pf[3] = packh2(s[2 * t + 1][2], s[2 * t + 1][3]);

            if (t == 3 && kt + 1 < NFT) {
                const int kn = (kt + 1) * 64;
#pragma unroll
                for (int j = 0; j < 8; j++) {
                    float2 b0 = *(const float2*)(bp0 + kn + 8 * j);
                    float2 b1 = *(const float2*)(bp1 + kn + 8 * j);
                    s[j][0] = b0.x - CSUB; s[j][1] = b0.y - CSUB;
                    s[j][2] = b1.x - CSUB; s[j][3] = b1.y - CSUB;
                }
            }
#pragma unroll
            for (int jp = 0; jp < 4; jp++) {
                uint32_t addr = kvb + FMATB
                    + (uint32_t)((16 * t + vrow) * FROWH + 16 * jp + vcol) * 2;
                uint32_t v4[4];
                ldmx4t(v4, addr);
                mma_f16(O[2 * jp],     pf, v4);
                mma_f16(O[2 * jp + 1], pf, v4 + 2);
            }
        }
    }

    // ---- final row-sum reduction (once) ----
    lA += __shfl_xor_sync(0xffffffffu, lA, 1);
    lA += __shfl_xor_sync(0xffffffffu, lA, 2);
    lB += __shfl_xor_sync(0xffffffffu, lB, 1);
    lB += __shfl_xor_sync(0xffffffffu, lB, 2);

    // ---- epilogue: normalize, split hi/lo bf16 for 3-term out-proj ----
    float iA = 1.f / lA, iB = 1.f / lB;
    size_t oA = ((size_t)b * SS + q0 + warp_m + (lane >> 2)) * DD + h * HD;
    size_t oB = oA + 8 * DD;
#pragma unroll
    for (int j = 0; j < 8; j++) {
        int d = 8 * j + 2 * (lane & 3);
        uint32_t hp, lp;
        split2(O[j][0] * iA, O[j][1] * iA, hp, lp);
        *(uint32_t*)(AOh + oA + d) = hp;
        *(uint32_t*)(AOl + oA + d) = lp;
        split2(O[j][2] * iB, O[j][3] * iB, hp, lp);
        *(uint32_t*)(AOh + oB + d) = hp;
        *(uint32_t*)(AOl + oB + d) = lp;
    }
}

// ---------------------------------------------------------------------------
extern "C" void kernel_launch(void* const* d_in, const int* in_sizes, int n_in,
                              void* d_out, int out_size)
{
    (void)in_sizes; (void)n_in; (void)out_size;
    const float* x         = (const float*)d_in[0];
    const float* attn_bias = (const float*)d_in[1];
    const float* qkv_w     = (const float*)d_in[2];
    const float* qkv_b     = (const float*)d_in[3];
    const float* out_w     = (const float*)d_in[4];
    const float* out_b     = (const float*)d_in[5];
    float* out = (float*)d_out;

    __nv_bfloat16 *ahi, *alo, *whi, *wlo;
    __half *qf, *kf, *vf;
    cudaGetSymbolAddress((void**)&ahi, g_ahi);
    cudaGetSymbolAddress((void**)&alo, g_alo);
    cudaGetSymbolAddress((void**)&whi, g_whi);
    cudaGetSymbolAddress((void**)&wlo, g_wlo);
    cudaGetSymbolAddress((void**)&qf,  g_qf);
    cudaGetSymbolAddress((void**)&kf,  g_kf);
    cudaGetSymbolAddress((void**)&vf,  g_vf);

    cudaFuncSetAttribute(gemm_mma_kernel,
                         cudaFuncAttributeMaxDynamicSharedMemorySize, SMEM_GEMM);
    cudaFuncSetAttribute(flash_mma_kernel,
                         cudaFuncAttributeMaxDynamicSharedMemorySize, FLASH_SMEM);

    // 1) split x and qkv_w into bf16 hi/lo
    {
        int n4 = MM * GK / 4;
        convert_kernel<<<(n4 + 255) / 256, 256>>>(x, ahi, alo, n4);
        int w4 = DQKV * GK / 4;
        convert_kernel<<<(w4 + 255) / 256, 256>>>(qkv_w, whi, wlo, w4);
    }
    // 2) QKV projection (3-term bf16); epilogue emits q/k/v single fp16
    gemm_mma_kernel<<<dim3(DQKV / BN, MM / BM), 256, SMEM_GEMM>>>(
        ahi, alo, whi, wlo, qkv_b, out /*unused*/, DQKV, 1);

    // 3) Flash attention, single-term fp16 -> ahi/alo (bf16 hi/lo)
    flash_mma_kernel<<<dim3(BB, HH, SS / 128), 256, FLASH_SMEM>>>(
        qf, kf, vf, attn_bias, ahi, alo);

    // 4) split out_w
    {
        int w4 = DD * DD / 4;
        convert_kernel<<<(w4 + 255) / 256, 256>>>(out_w, whi, wlo, w4);
    }
    // 5) Output projection (3-term bf16) -> d_out
    gemm_mma_kernel<<<dim3(DD / BN, MM / BM), 256, SMEM_GEMM>>>(
        ahi, alo, whi, wlo, out_b, out, DD, 0);
}

// round 11
// speedup vs baseline: 2.1463x; 1.6790x over previous
#include <cuda_runtime.h>
#include <cuda_bf16.h>
#include <cuda_fp16.h>
#include <cstdint>
#include <math.h>

// Problem constants
#define BB   4
#define SS   2048
#define DD   1024
#define HH   16
#define HD   64
#define DQKV 3072
#define MM   (BB*SS)          // 8192
#define GK   1024

// GEMM tiling (single-term fp16)
#define BM 128
#define BN 128
#define BK 32
#define NKT (GK/BK)           // 32
#define ROWH 40               // padded row stride in halfs (80B)
#define MATH (BM*ROWH)        // 5120 halfs per matrix tile
#define STAGEH (2*MATH)       // A + W per stage

// Flash smem layout: 3-stage ring, single-fp16 K and V per stage
#define FROWH 72                      // K/V row stride in halfs (144B)
#define FMATB (64*FROWH*2)            // 9216 B per 64x64 fp16 matrix
#define FKVB  (2*FMATB)               // 18432 B per stage (K, V)
#define FLASH_SMEM (3*FKVB)           // 55296 B
#define NFT (SS/64)                   // 32 key tiles
#define CSUB 6.0f                     // softmax shift: p = exp(s - 6) fits fp16

// Scratch (allocation-free: device globals)
__device__ __half g_af[(size_t)MM * GK];   // x fp16, then ao fp16 (reused)
__device__ __half g_wf[(size_t)DQKV * GK]; // qkv_w fp16, then out_w fp16
__device__ __half g_qf[(size_t)MM * DD];   // [b,h,s,d] fp16, q pre-scaled
__device__ __half g_kf[(size_t)MM * DD];
__device__ __half g_vf[(size_t)MM * DD];

// ---------------------------------------------------------------------------
// PTX helpers (sm_80-portable: cp.async, ldmatrix, mma.sync)
// ---------------------------------------------------------------------------
__device__ __forceinline__ uint32_t smem_u32(const void* p) {
    uint32_t a;
    asm("{ .reg .u64 t; cvta.to.shared.u64 t, %1; cvt.u32.u64 %0, t; }"
        : "=r"(a) : "l"(p));
    return a;
}
__device__ __forceinline__ void cp_async16(uint32_t dst, const void* src) {
    asm volatile("cp.async.cg.shared.global [%0], [%1], 16;" :: "r"(dst), "l"(src));
}
__device__ __forceinline__ void ldmx4(uint32_t* r, uint32_t addr) {
    asm volatile("ldmatrix.sync.aligned.m8n8.x4.shared.b16 {%0,%1,%2,%3}, [%4];"
                 : "=r"(r[0]), "=r"(r[1]), "=r"(r[2]), "=r"(r[3]) : "r"(addr));
}
__device__ __forceinline__ void ldmx4t(uint32_t* r, uint32_t addr) {
    asm volatile("ldmatrix.sync.aligned.m8n8.x4.trans.shared.b16 {%0,%1,%2,%3}, [%4];"
                 : "=r"(r[0]), "=r"(r[1]), "=r"(r[2]), "=r"(r[3]) : "r"(addr));
}
__device__ __forceinline__ void mma_f16(float* d, const uint32_t* a, const uint32_t* b) {
    asm("mma.sync.aligned.m16n8k16.row.col.f32.f16.f16.f32 "
        "{%0,%1,%2,%3}, {%4,%5,%6,%7}, {%8,%9}, {%0,%1,%2,%3};"
        : "+f"(d[0]), "+f"(d[1]), "+f"(d[2]), "+f"(d[3])
        : "r"(a[0]), "r"(a[1]), "r"(a[2]), "r"(a[3]), "r"(b[0]), "r"(b[1]));
}
__device__ __forceinline__ uint32_t packh2(float x, float y) {
    __half2 h = __floats2half2_rn(x, y);   // low = x, high = y
    return *reinterpret_cast<uint32_t*>(&h);
}

// ---------------------------------------------------------------------------
// fp32 -> fp16 cast (bulk)
// ---------------------------------------------------------------------------
__global__ __launch_bounds__(256) void convert_f16_kernel(
    const float* __restrict__ in, __half* __restrict__ o, int n4)
{
    int i = blockIdx.x * blockDim.x + threadIdx.x;
    if (i >= n4) return;
    float4 v = *(const float4*)(in + (size_t)i * 4);
    uint32_t* op = (uint32_t*)(o + (size_t)i * 4);
    op[0] = packh2(v.x, v.y);
    op[1] = packh2(v.z, v.w);
}

// ---------------------------------------------------------------------------
// HMMA GEMM (single fp16): C = A @ W^T + bias. mode 0: fp32 C.
// mode 1: QKV epilogue -> q(*0.125)/k/v fp16 in [b,h,s,d].
// ---------------------------------------------------------------------------
__global__ __launch_bounds__(256, 2) void gemm_mma_kernel(
    const __half* __restrict__ Af, const __half* __restrict__ Wf,
    const float* __restrict__ bias, float* __restrict__ C, int N, int mode)
{
    extern __shared__ __half smg[];
    const uint32_t sb = smem_u32(smg);
    const int tid  = threadIdx.x;
    const int wid  = tid >> 5;
    const int lane = tid & 31;
    const int m0 = blockIdx.y * BM;
    const int n0 = blockIdx.x * BN;
    const int warp_m = (wid >> 2) * 64;
    const int warp_n = (wid & 3) * 32;

    float acc[4][4][4];
#pragma unroll
    for (int i = 0; i < 4; i++)
#pragma unroll
        for (int j = 0; j < 4; j++)
#pragma unroll
            for (int r = 0; r < 4; r++) acc[i][j][r] = 0.f;

    auto load_stage = [&](int kt, int st) {
        const int kcol = kt * BK;
#pragma unroll
        for (int t = 0; t < 4; t++) {
            int c   = tid + t * 256;          // 0..1023
            int mat = c >> 9;                 // 0=A, 1=W
            int idx = c & 511;
            int row = idx >> 2;               // 0..127
            int c16 = idx & 3;                // 16B chunk along k
            int grow = (mat == 0 ? m0 : n0) + row;
            const __half* src = (mat == 0 ? Af : Wf) + (size_t)grow * GK + kcol + c16 * 8;
            uint32_t dst = sb + (uint32_t)(st * STAGEH + mat * MATH + row * ROWH + c16 * 8) * 2;
            cp_async16(dst, src);
        }
        asm volatile("cp.async.commit_group;" ::: "memory");
    };

    load_stage(0, 0);

    for (int kt = 0; kt < NKT; kt++) {
        const int st = kt & 1;
        if (kt + 1 < NKT) {
            load_stage(kt + 1, st ^ 1);
            asm volatile("cp.async.wait_group 1;" ::: "memory");
        } else {
            asm volatile("cp.async.wait_group 0;" ::: "memory");
        }
        __syncthreads();

        const uint32_t aB = sb + (uint32_t)(st * STAGEH) * 2;
        const uint32_t wB = aB + MATH * 2;

#pragma unroll
        for (int ks = 0; ks < 2; ks++) {
            const int kk = ks * 16;
            uint32_t a4[4][4], b4[4][2];
#pragma unroll
            for (int i = 0; i < 4; i++) {
                uint32_t off = (uint32_t)((warp_m + i * 16 + (lane & 15)) * ROWH
                                          + kk + (lane >> 4) * 8) * 2;
                ldmx4(a4[i], aB + off);
            }
#pragma unroll
            for (int jp2 = 0; jp2 < 2; jp2++) {
                int g = lane >> 3;
                uint32_t off = (uint32_t)((warp_n + (2 * jp2 + (g >> 1)) * 8
                                           + (lane & 7)) * ROWH
                                          + kk + (g & 1) * 8) * 2;
                uint32_t r4[4];
                ldmx4(r4, wB + off);
                b4[2 * jp2][0] = r4[0]; b4[2 * jp2][1] = r4[1];
                b4[2 * jp2 + 1][0] = r4[2]; b4[2 * jp2 + 1][1] = r4[3];
            }
#pragma unroll
            for (int i = 0; i < 4; i++)
#pragma unroll
                for (int j = 0; j < 4; j++) mma_f16(acc[i][j], a4[i], b4[j]);
        }
        __syncthreads();
    }

    if (mode == 0) {
#pragma unroll
        for (int i = 0; i < 4; i++) {
#pragma unroll
            for (int j = 0; j < 4; j++) {
                int m = m0 + warp_m + i * 16 + (lane >> 2);
                int n = n0 + warp_n + j * 8 + (lane & 3) * 2;
                float2 bv = *(const float2*)(bias + n);
                float2 o0 = { acc[i][j][0] + bv.x, acc[i][j][1] + bv.y };
                float2 o1 = { acc[i][j][2] + bv.x, acc[i][j][3] + bv.y };
                *(float2*)(C + (size_t)m * N + n) = o0;
                *(float2*)(C + (size_t)(m + 8) * N + n) = o1;
            }
        }
    } else {
#pragma unroll
        for (int i = 0; i < 4; i++) {
#pragma unroll
            for (int j = 0; j < 4; j++) {
                int m = m0 + warp_m + i * 16 + (lane >> 2);
                int n = n0 + warp_n + j * 8 + (lane & 3) * 2;
                float2 bv = *(const float2*)(bias + n);
                int sel = n >> 10;
                int hh  = (n & 1023) >> 6;
                int d   = n & 63;
                float sc = (sel == 0) ? 0.125f : 1.0f;
                __half* dst = (sel == 0) ? g_qf : (sel == 1) ? g_kf : g_vf;
#pragma unroll
                for (int rr = 0; rr < 2; rr++) {
                    int mm = m + rr * 8;
                    float vx = (acc[i][j][rr * 2 + 0] + bv.x) * sc;
                    float vy = (acc[i][j][rr * 2 + 1] + bv.y) * sc;
                    size_t idx = (((size_t)(mm >> 11) * HH + hh) * SS + (mm & 2047)) * HD + d;
                    *(uint32_t*)(dst + idx) = packh2(vx, vy);
                }
            }
        }
    }
}
static constexpr int SMEM_GEMM = 2 * STAGEH * 2;  // 40960 B

// ---------------------------------------------------------------------------
// Flash attention: single-term fp16 HMMA for QK and PV.
// Fixed-reference softmax shifted by CSUB so p fits fp16 range.
// 256 thr, warp = 16 q rows, 3-stage K/V ring, bias LDG'd into accumulators.
// Epilogue writes ao as single fp16 (feeds single-term out-proj).
// ---------------------------------------------------------------------------
__global__ __launch_bounds__(256, 2) void flash_mma_kernel(
    const __half* __restrict__ Qf, const __half* __restrict__ Kf,
    const __half* __restrict__ Vf, const float* __restrict__ bias,
    __half* __restrict__ AOf)
{
    extern __shared__ char smc[];
    const uint32_t sb = smem_u32(smc);
    const int tid = threadIdx.x, wid = tid >> 5, lane = tid & 31;
    const int b = blockIdx.x, h = blockIdx.y, q0 = blockIdx.z * 128;
    const int warp_m = wid * 16;
    const size_t bh = ((size_t)b * HH + h) * SS;

    // Q fragments (fp16, pre-scaled), reused over all key tiles
    uint32_t qf[4][4];
    {
        size_t rA = (bh + q0 + warp_m + (lane >> 2)) * HD;
        size_t rB = rA + 8 * HD;
        int c0 = 2 * (lane & 3);
#pragma unroll
        for (int t = 0; t < 4; t++) {
            qf[t][0] = *(const uint32_t*)(Qf + rA + 16 * t + c0);
            qf[t][1] = *(const uint32_t*)(Qf + rB + 16 * t + c0);
            qf[t][2] = *(const uint32_t*)(Qf + rA + 16 * t + 8 + c0);
            qf[t][3] = *(const uint32_t*)(Qf + rB + 16 * t + 8 + c0);
        }
    }

    const float* bp0 = bias + ((size_t)h * SS + q0 + warp_m + (lane >> 2)) * SS
                       + 2 * (lane & 3);
    const float* bp1 = bp0 + 8 * SS;

    float O[8][4];
#pragma unroll
    for (int j = 0; j < 8; j++)
#pragma unroll
        for (int r = 0; r < 4; r++) O[j][r] = 0.f;
    float lA = 0.f, lB = 0.f;

    // s preloaded with (bias - CSUB)
    float s[8][4];
#pragma unroll
    for (int j = 0; j < 8; j++) {
        float2 b0 = *(const float2*)(bp0 + 8 * j);
        float2 b1 = *(const float2*)(bp1 + 8 * j);
        s[j][0] = b0.x - CSUB; s[j][1] = b0.y - CSUB;
        s[j][2] = b1.x - CSUB; s[j][3] = b1.y - CSUB;
    }

    auto load_stage = [&](int kt) {
        if (kt < NFT) {
            uint32_t base = sb + (kt % 3) * FKVB;
            int k0 = kt * 64;
#pragma unroll
            for (int t = 0; t < 4; t++) {
                int c = tid + t * 256;                   // 0..1023
                int mat = c >> 9;                        // 0=K, 1=V
                int idx = c & 511;
                int row = idx >> 3, ch = idx & 7;
                const __half* src = mat ? Vf : Kf;
                cp_async16(base + mat * FMATB + (uint32_t)(row * FROWH + ch * 8) * 2,
                           src + (bh + k0 + row) * HD + ch * 8);
            }
        }
        asm volatile("cp.async.commit_group;" ::: "memory");
    };

    load_stage(0);
    load_stage(1);

    const int krow = ((lane >> 4) & 1) * 8 + (lane & 7);
    const int kcol = ((lane >> 3) & 1) * 8;
    const int vrow = ((lane >> 3) & 1) * 8 + (lane & 7);
    const int vcol = ((lane >> 4) & 1) * 8;

    for (int kt = 0; kt < NFT; kt++) {
        __syncthreads();                  // all warps done with stage (kt-1)%3
        load_stage(kt + 2);
        asm volatile("cp.async.wait_group 2;" ::: "memory");  // stage kt ready

        const uint32_t kvb = sb + (kt % 3) * FKVB;

        // ---- S (= bias - C) += Q K^T, single fp16 term ----
#pragma unroll
        for (int t = 0; t < 4; t++) {
#pragma unroll
            for (int jp = 0; jp < 4; jp++) {
                uint32_t addr = kvb + (uint32_t)((jp * 16 + krow) * FROWH
                                                 + 16 * t + kcol) * 2;
                uint32_t k4[4];
                ldmx4(k4, addr);
                mma_f16(s[2 * jp],     qf[t], k4);
                mma_f16(s[2 * jp + 1], qf[t], k4 + 2);
            }
        }

        // ---- p = exp(s); fp32 partial row sums ----
#pragma unroll
        for (int j = 0; j < 8; j++) {
            s[j][0] = __expf(s[j][0]);
            s[j][1] = __expf(s[j][1]);
            s[j][2] = __expf(s[j][2]);
            s[j][3] = __expf(s[j][3]);
            lA += s[j][0] + s[j][1];
            lB += s[j][2] + s[j][3];
        }

        // ---- O += P V, single fp16 term; bias prefetch in last chunk ----
#pragma unroll
        for (int t = 0; t < 4; t++) {
            uint32_t pf[4];
            pf[0] = packh2(s[2 * t][0],     s[2 * t][1]);
            pf[1] = packh2(s[2 * t][2],     s[2 * t][3]);
            pf[2] = packh2(s[2 * t + 1][0], s[2 * t + 1][1]);
            pf[3] = packh2(s[2 * t + 1][2], s[2 * t + 1][3]);

            if (t == 3 && kt + 1 < NFT) {
                const int kn = (kt + 1) * 64;
#pragma unroll
                for (int j = 0; j < 8; j++) {
                    float2 b0 = *(const float2*)(bp0 + kn + 8 * j);
                    float2 b1 = *(const float2*)(bp1 + kn + 8 * j);
                    s[j][0] = b0.x - CSUB; s[j][1] = b0.y - CSUB;
                    s[j][2] = b1.x - CSUB; s[j][3] = b1.y - CSUB;
                }
            }
#pragma unroll
            for (int jp = 0; jp < 4; jp++) {
                uint32_t addr = kvb + FMATB
                    + (uint32_t)((16 * t + vrow) * FROWH + 16 * jp + vcol) * 2;
                uint32_t v4[4];
                ldmx4t(v4, addr);
                mma_f16(O[2 * jp],     pf, v4);
                mma_f16(O[2 * jp + 1], pf, v4 + 2);
            }
        }
    }

    // ---- final row-sum reduction (once) ----
    lA += __shfl_xor_sync(0xffffffffu, lA, 1);
    lA += __shfl_xor_sync(0xffffffffu, lA, 2);
    lB += __shfl_xor_sync(0xffffffffu, lB, 1);
    lB += __shfl_xor_sync(0xffffffffu, lB, 2);

    // ---- epilogue: normalize, write ao as single fp16 ----
    float iA = 1.f / lA, iB = 1.f / lB;
    size_t oA = ((size_t)b * SS + q0 + warp_m + (lane >> 2)) * DD + h * HD;
    size_t oB = oA + 8 * DD;
#pragma unroll
    for (int j = 0; j < 8; j++) {
        int d = 8 * j + 2 * (lane & 3);
        *(uint32_t*)(AOf + oA + d) = packh2(O[j][0] * iA, O[j][1] * iA);
        *(uint32_t*)(AOf + oB + d) = packh2(O[j][2] * iB, O[j][3] * iB);
    }
}

// ---------------------------------------------------------------------------
extern "C" void kernel_launch(void* const* d_in, const int* in_sizes, int n_in,
                              void* d_out, int out_size)
{
    (void)in_sizes; (void)n_in; (void)out_size;
    const float* x         = (const float*)d_in[0];
    const float* attn_bias = (const float*)d_in[1];
    const float* qkv_w     = (const float*)d_in[2];
    const float* qkv_b     = (const float*)d_in[3];
    const float* out_w     = (const float*)d_in[4];
    const float* out_b     = (const float*)d_in[5];
    float* out = (float*)d_out;

    __half *af, *wf, *qf, *kf, *vf;
    cudaGetSymbolAddress((void**)&af, g_af);
    cudaGetSymbolAddress((void**)&wf, g_wf);
    cudaGetSymbolAddress((void**)&qf, g_qf);
    cudaGetSymbolAddress((void**)&kf, g_kf);
    cudaGetSymbolAddress((void**)&vf, g_vf);

    cudaFuncSetAttribute(gemm_mma_kernel,
                         cudaFuncAttributeMaxDynamicSharedMemorySize, SMEM_GEMM);
    cudaFuncSetAttribute(flash_mma_kernel,
                         cudaFuncAttributeMaxDynamicSharedMemorySize, FLASH_SMEM);

    // 1) cast x and qkv_w to fp16
    {
        int n4 = MM * GK / 4;
        convert_f16_kernel<<<(n4 + 255) / 256, 256>>>(x, af, n4);
        int w4 = DQKV * GK / 4;
        convert_f16_kernel<<<(w4 + 255) / 256, 256>>>(qkv_w, wf, w4);
    }
    // 2) QKV projection (single fp16); epilogue emits q/k/v fp16 [b,h,s,d]
    gemm_mma_kernel<<<dim3(DQKV / BN, MM / BM), 256, SMEM_GEMM>>>(
        af, wf, qkv_b, out /*unused*/, DQKV, 1);

    // 3) Flash attention, single-term fp16 -> ao fp16 (reuses g_af)
    flash_mma_kernel<<<dim3(BB, HH, SS / 128), 256, FLASH_SMEM>>>(
        qf, kf, vf, attn_bias, af);

    // 4) cast out_w to fp16
    {
        int w4 = DD * DD / 4;
        convert_f16_kernel<<<(w4 + 255) / 256, 256>>>(out_w, wf, w4);
    }
    // 5) Output projection (single fp16) -> d_out
    gemm_mma_kernel<<<dim3(DD / BN, MM / BM), 256, SMEM_GEMM>>>(
        af, wf, out_b, out, DD, 0);
}

// round 12
// speedup vs baseline: 2.1816x; 1.0164x over previous
#include <cuda_runtime.h>
#include <cuda_bf16.h>
#include <cuda_fp16.h>
#include <cstdint>
#include <math.h>

// Problem constants
#define BB   4
#define SS   2048
#define DD   1024
#define HH   16
#define HD   64
#define DQKV 3072
#define MM   (BB*SS)          // 8192
#define GK   1024

// GEMM tiling (single-term fp16)
#define BM 128
#define BN 128
#define BK 32
#define NKT (GK/BK)           // 32
#define ROWH 40               // padded row stride in halfs (80B)
#define MATH (BM*ROWH)        // 5120 halfs per matrix tile
#define STAGEH (2*MATH)       // A + W per stage

// Flash smem layout: 3-stage ring, single-fp16 K and V per stage
#define FROWH 72                      // K/V row stride in halfs (144B)
#define FMATB (64*FROWH*2)            // 9216 B per 64x64 fp16 matrix
#define FKVB  (2*FMATB)               // 18432 B per stage (K, V)
#define FLASH_SMEM (3*FKVB)           // 55296 B -> 2 CTAs/SM
#define NFT (SS/64)                   // 32 key tiles
#define CSUB 6.0f                     // softmax shift: p = exp(s - 6) fits fp16

// Scratch (allocation-free: device globals)
__device__ __half g_af[(size_t)MM * GK];   // x fp16, then ao fp16 (reused)
__device__ __half g_wf[(size_t)DQKV * GK]; // qkv_w fp16, then out_w fp16
__device__ __half g_qf[(size_t)MM * DD];   // [b,h,s,d] fp16, q pre-scaled
__device__ __half g_kf[(size_t)MM * DD];
__device__ __half g_vf[(size_t)MM * DD];

// ---------------------------------------------------------------------------
// PTX helpers (sm_80-portable: cp.async, ldmatrix, mma.sync)
// ---------------------------------------------------------------------------
__device__ __forceinline__ uint32_t smem_u32(const void* p) {
    uint32_t a;
    asm("{ .reg .u64 t; cvta.to.shared.u64 t, %1; cvt.u32.u64 %0, t; }"
        : "=r"(a) : "l"(p));
    return a;
}
__device__ __forceinline__ void cp_async16(uint32_t dst, const void* src) {
    asm volatile("cp.async.cg.shared.global [%0], [%1], 16;" :: "r"(dst), "l"(src));
}
__device__ __forceinline__ void ldmx4(uint32_t* r, uint32_t addr) {
    asm volatile("ldmatrix.sync.aligned.m8n8.x4.shared.b16 {%0,%1,%2,%3}, [%4];"
                 : "=r"(r[0]), "=r"(r[1]), "=r"(r[2]), "=r"(r[3]) : "r"(addr));
}
__device__ __forceinline__ void ldmx4t(uint32_t* r, uint32_t addr) {
    asm volatile("ldmatrix.sync.aligned.m8n8.x4.trans.shared.b16 {%0,%1,%2,%3}, [%4];"
                 : "=r"(r[0]), "=r"(r[1]), "=r"(r[2]), "=r"(r[3]) : "r"(addr));
}
__device__ __forceinline__ void mma_f16(float* d, const uint32_t* a, const uint32_t* b) {
    asm("mma.sync.aligned.m16n8k16.row.col.f32.f16.f16.f32 "
        "{%0,%1,%2,%3}, {%4,%5,%6,%7}, {%8,%9}, {%0,%1,%2,%3};"
        : "+f"(d[0]), "+f"(d[1]), "+f"(d[2]), "+f"(d[3])
        : "r"(a[0]), "r"(a[1]), "r"(a[2]), "r"(a[3]), "r"(b[0]), "r"(b[1]));
}
__device__ __forceinline__ uint32_t packh2(float x, float y) {
    __half2 h = __floats2half2_rn(x, y);   // low = x, high = y
    return *reinterpret_cast<uint32_t*>(&h);
}

// ---------------------------------------------------------------------------
// fp32 -> fp16 cast (bulk)
// ---------------------------------------------------------------------------
__global__ __launch_bounds__(256) void convert_f16_kernel(
    const float* __restrict__ in, __half* __restrict__ o, int n4)
{
    int i = blockIdx.x * blockDim.x + threadIdx.x;
    if (i >= n4) return;
    float4 v = *(const float4*)(in + (size_t)i * 4);
    uint32_t* op = (uint32_t*)(o + (size_t)i * 4);
    op[0] = packh2(v.x, v.y);
    op[1] = packh2(v.z, v.w);
}

// ---------------------------------------------------------------------------
// HMMA GEMM (single fp16): C = A @ W^T + bias. mode 0: fp32 C.
// mode 1: QKV epilogue -> q(*0.125)/k/v fp16 in [b,h,s,d].
// ---------------------------------------------------------------------------
__global__ __launch_bounds__(256, 2) void gemm_mma_kernel(
    const __half* __restrict__ Af, const __half* __restrict__ Wf,
    const float* __restrict__ bias, float* __restrict__ C, int N, int mode)
{
    extern __shared__ __half smg[];
    const uint32_t sb = smem_u32(smg);
    const int tid  = threadIdx.x;
    const int wid  = tid >> 5;
    const int lane = tid & 31;
    const int m0 = blockIdx.y * BM;
    const int n0 = blockIdx.x * BN;
    const int warp_m = (wid >> 2) * 64;
    const int warp_n = (wid & 3) * 32;

    float acc[4][4][4];
#pragma unroll
    for (int i = 0; i < 4; i++)
#pragma unroll
        for (int j = 0; j < 4; j++)
#pragma unroll
            for (int r = 0; r < 4; r++) acc[i][j][r] = 0.f;

    auto load_stage = [&](int kt, int st) {
        const int kcol = kt * BK;
#pragma unroll
        for (int t = 0; t < 4; t++) {
            int c   = tid + t * 256;          // 0..1023
            int mat = c >> 9;                 // 0=A, 1=W
            int idx = c & 511;
            int row = idx >> 2;               // 0..127
            int c16 = idx & 3;                // 16B chunk along k
            int grow = (mat == 0 ? m0 : n0) + row;
            const __half* src = (mat == 0 ? Af : Wf) + (size_t)grow * GK + kcol + c16 * 8;
            uint32_t dst = sb + (uint32_t)(st * STAGEH + mat * MATH + row * ROWH + c16 * 8) * 2;
            cp_async16(dst, src);
        }
        asm volatile("cp.async.commit_group;" ::: "memory");
    };

    load_stage(0, 0);

    for (int kt = 0; kt < NKT; kt++) {
        const int st = kt & 1;
        if (kt + 1 < NKT) {
            load_stage(kt + 1, st ^ 1);
            asm volatile("cp.async.wait_group 1;" ::: "memory");
        } else {
            asm volatile("cp.async.wait_group 0;" ::: "memory");
        }
        __syncthreads();

        const uint32_t aB = sb + (uint32_t)(st * STAGEH) * 2;
        const uint32_t wB = aB + MATH * 2;

#pragma unroll
        for (int ks = 0; ks < 2; ks++) {
            const int kk = ks * 16;
            uint32_t a4[4][4], b4[4][2];
#pragma unroll
            for (int i = 0; i < 4; i++) {
                uint32_t off = (uint32_t)((warp_m + i * 16 + (lane & 15)) * ROWH
                                          + kk + (lane >> 4) * 8) * 2;
                ldmx4(a4[i], aB + off);
            }
#pragma unroll
            for (int jp2 = 0; jp2 < 2; jp2++) {
                int g = lane >> 3;
                uint32_t off = (uint32_t)((warp_n + (2 * jp2 + (g >> 1)) * 8
                                           + (lane & 7)) * ROWH
                                          + kk + (g & 1) * 8) * 2;
                uint32_t r4[4];
                ldmx4(r4, wB + off);
                b4[2 * jp2][0] = r4[0]; b4[2 * jp2][1] = r4[1];
                b4[2 * jp2 + 1][0] = r4[2]; b4[2 * jp2 + 1][1] = r4[3];
            }
#pragma unroll
            for (int i = 0; i < 4; i++)
#pragma unroll
                for (int j = 0; j < 4; j++) mma_f16(acc[i][j], a4[i], b4[j]);
        }
        __syncthreads();
    }

    if (mode == 0) {
#pragma unroll
        for (int i = 0; i < 4; i++) {
#pragma unroll
            for (int j = 0; j < 4; j++) {
                int m = m0 + warp_m + i * 16 + (lane >> 2);
                int n = n0 + warp_n + j * 8 + (lane & 3) * 2;
                float2 bv = *(const float2*)(bias + n);
                float2 o0 = { acc[i][j][0] + bv.x, acc[i][j][1] + bv.y };
                float2 o1 = { acc[i][j][2] + bv.x, acc[i][j][3] + bv.y };
                *(float2*)(C + (size_t)m * N + n) = o0;
                *(float2*)(C + (size_t)(m + 8) * N + n) = o1;
            }
        }
    } else {
#pragma unroll
        for (int i = 0; i < 4; i++) {
#pragma unroll
            for (int j = 0; j < 4; j++) {
                int m = m0 + warp_m + i * 16 + (lane >> 2);
                int n = n0 + warp_n + j * 8 + (lane & 3) * 2;
                float2 bv = *(const float2*)(bias + n);
                int sel = n >> 10;
                int hh  = (n & 1023) >> 6;
                int d   = n & 63;
                float sc = (sel == 0) ? 0.125f : 1.0f;
                __half* dst = (sel == 0) ? g_qf : (sel == 1) ? g_kf : g_vf;
#pragma unroll
                for (int rr = 0; rr < 2; rr++) {
                    int mm = m + rr * 8;
                    float vx = (acc[i][j][rr * 2 + 0] + bv.x) * sc;
                    float vy = (acc[i][j][rr * 2 + 1] + bv.y) * sc;
                    size_t idx = (((size_t)(mm >> 11) * HH + hh) * SS + (mm & 2047)) * HD + d;
                    *(uint32_t*)(dst + idx) = packh2(vx, vy);
                }
            }
        }
    }
}
static constexpr int SMEM_GEMM = 2 * STAGEH * 2;  // 40960 B

// ---------------------------------------------------------------------------
// Flash attention: single-term fp16, m=32 per warp (halves LDSM traffic).
// 128-thread CTAs (4 warps x 32 q rows), 2 CTAs/SM, 3-stage K/V ring,
// fixed-reference shifted softmax, bias LDG'd into accumulators.
// ---------------------------------------------------------------------------
__global__ __launch_bounds__(128, 2) void flash_mma_kernel(
    const __half* __restrict__ Qf, const __half* __restrict__ Kf,
    const __half* __restrict__ Vf, const float* __restrict__ bias,
    __half* __restrict__ AOf)
{
    extern __shared__ char smc[];
    const uint32_t sb = smem_u32(smc);
    const int tid = threadIdx.x, wid = tid >> 5, lane = tid & 31;
    const int b = blockIdx.x, h = blockIdx.y, q0 = blockIdx.z * 128;
    const int warp_m = wid * 32;
    const size_t bh = ((size_t)b * HH + h) * SS;

    // Q fragments for two m16 tiles (fp16, pre-scaled)
    uint32_t qf[2][4][4];
#pragma unroll
    for (int i = 0; i < 2; i++) {
        size_t rA = (bh + q0 + warp_m + i * 16 + (lane >> 2)) * HD;
        size_t rB = rA + 8 * HD;
        int c0 = 2 * (lane & 3);
#pragma unroll
        for (int t = 0; t < 4; t++) {
            qf[i][t][0] = *(const uint32_t*)(Qf + rA + 16 * t + c0);
            qf[i][t][1] = *(const uint32_t*)(Qf + rB + 16 * t + c0);
            qf[i][t][2] = *(const uint32_t*)(Qf + rA + 16 * t + 8 + c0);
            qf[i][t][3] = *(const uint32_t*)(Qf + rB + 16 * t + 8 + c0);
        }
    }

    // bias row pointers per m-tile
    const float* bp0[2];
    const float* bp1[2];
#pragma unroll
    for (int i = 0; i < 2; i++) {
        bp0[i] = bias + ((size_t)h * SS + q0 + warp_m + i * 16 + (lane >> 2)) * SS
                 + 2 * (lane & 3);
        bp1[i] = bp0[i] + 8 * SS;
    }

    float O[2][8][4];
#pragma unroll
    for (int i = 0; i < 2; i++)
#pragma unroll
        for (int j = 0; j < 8; j++)
#pragma unroll
            for (int r = 0; r < 4; r++) O[i][j][r] = 0.f;
    float lA[2] = {0.f, 0.f}, lB[2] = {0.f, 0.f};

    // s[i][j][r] preloaded with (bias - CSUB)
    float s[2][8][4];
#pragma unroll
    for (int i = 0; i < 2; i++)
#pragma unroll
        for (int j = 0; j < 8; j++) {
            float2 b0 = *(const float2*)(bp0[i] + 8 * j);
            float2 b1 = *(const float2*)(bp1[i] + 8 * j);
            s[i][j][0] = b0.x - CSUB; s[i][j][1] = b0.y - CSUB;
            s[i][j][2] = b1.x - CSUB; s[i][j][3] = b1.y - CSUB;
        }

    auto load_stage = [&](int kt) {
        if (kt < NFT) {
            uint32_t base = sb + (kt % 3) * FKVB;
            int k0 = kt * 64;
#pragma unroll
            for (int t = 0; t < 8; t++) {
                int c = tid + t * 128;                   // 0..1023
                int mat = c >> 9;                        // 0=K, 1=V
                int idx = c & 511;
                int row = idx >> 3, ch = idx & 7;
                const __half* src = mat ? Vf : Kf;
                cp_async16(base + mat * FMATB + (uint32_t)(row * FROWH + ch * 8) * 2,
                           src + (bh + k0 + row) * HD + ch * 8);
            }
        }
        asm volatile("cp.async.commit_group;" ::: "memory");
    };

    load_stage(0);
    load_stage(1);

    const int krow = ((lane >> 4) & 1) * 8 + (lane & 7);
    const int kcol = ((lane >> 3) & 1) * 8;
    const int vrow = ((lane >> 3) & 1) * 8 + (lane & 7);
    const int vcol = ((lane >> 4) & 1) * 8;

    for (int kt = 0; kt < NFT; kt++) {
        __syncthreads();                  // all warps done with stage (kt-1)%3
        load_stage(kt + 2);
        asm volatile("cp.async.wait_group 2;" ::: "memory");  // stage kt ready

        const uint32_t kvb = sb + (kt % 3) * FKVB;

        // ---- S (= bias - C) += Q K^T; K frags shared by both m-tiles ----
#pragma unroll
        for (int t = 0; t < 4; t++) {
#pragma unroll
            for (int c = 0; c < 4; c++) {     // 16-key chunks
                uint32_t addr = kvb + (uint32_t)((c * 16 + krow) * FROWH
                                                 + 16 * t + kcol) * 2;
                uint32_t k4[4];
                ldmx4(k4, addr);
                mma_f16(s[0][2 * c],     qf[0][t], k4);
                mma_f16(s[0][2 * c + 1], qf[0][t], k4 + 2);
                mma_f16(s[1][2 * c],     qf[1][t], k4);
                mma_f16(s[1][2 * c + 1], qf[1][t], k4 + 2);
            }
        }

        // ---- p = exp(s); fp32 partial row sums ----
#pragma unroll
        for (int i = 0; i < 2; i++)
#pragma unroll
            for (int j = 0; j < 8; j++) {
                s[i][j][0] = __expf(s[i][j][0]);
                s[i][j][1] = __expf(s[i][j][1]);
                s[i][j][2] = __expf(s[i][j][2]);
                s[i][j][3] = __expf(s[i][j][3]);
                lA[i] += s[i][j][0] + s[i][j][1];
                lB[i] += s[i][j][2] + s[i][j][3];
            }

        // ---- O += P V; V frags shared by both m-tiles ----
#pragma unroll
        for (int t = 0; t < 4; t++) {         // 16-key chunks
            uint32_t pf[2][4];
#pragma unroll
            for (int i = 0; i < 2; i++) {
                pf[i][0] = packh2(s[i][2 * t][0],     s[i][2 * t][1]);
                pf[i][1] = packh2(s[i][2 * t][2],     s[i][2 * t][3]);
                pf[i][2] = packh2(s[i][2 * t + 1][0], s[i][2 * t + 1][1]);
                pf[i][3] = packh2(s[i][2 * t + 1][2], s[i][2 * t + 1][3]);
            }

            if (t == 3 && kt + 1 < NFT) {
                // s fully consumed: prefetch next tile's bias
                const int kn = (kt + 1) * 64;
#pragma unroll
                for (int i = 0; i < 2; i++)
#pragma unroll
                    for (int j = 0; j < 8; j++) {
                        float2 b0 = *(const float2*)(bp0[i] + kn + 8 * j);
                        float2 b1 = *(const float2*)(bp1[i] + kn + 8 * j);
                        s[i][j][0] = b0.x - CSUB; s[i][j][1] = b0.y - CSUB;
                        s[i][j][2] = b1.x - CSUB; s[i][j][3] = b1.y - CSUB;
                    }
            }
#pragma unroll
            for (int jp = 0; jp < 4; jp++) {
                uint32_t addr = kvb + FMATB
                    + (uint32_t)((16 * t + vrow) * FROWH + 16 * jp + vcol) * 2;
                uint32_t v4[4];
                ldmx4t(v4, addr);
                mma_f16(O[0][2 * jp],     pf[0], v4);
                mma_f16(O[0][2 * jp + 1], pf[0], v4 + 2);
                mma_f16(O[1][2 * jp],     pf[1], v4);
                mma_f16(O[1][2 * jp + 1], pf[1], v4 + 2);
            }
        }
    }

    // ---- final row-sum reduction (once) ----
#pragma unroll
    for (int i = 0; i < 2; i++) {
        lA[i] += __shfl_xor_sync(0xffffffffu, lA[i], 1);
        lA[i] += __shfl_xor_sync(0xffffffffu, lA[i], 2);
        lB[i] += __shfl_xor_sync(0xffffffffu, lB[i], 1);
        lB[i] += __shfl_xor_sync(0xffffffffu, lB[i], 2);
    }

    // ---- epilogue: normalize, write ao as single fp16 ----
#pragma unroll
    for (int i = 0; i < 2; i++) {
        float iA = 1.f / lA[i], iB = 1.f / lB[i];
        size_t oA = ((size_t)b * SS + q0 + warp_m + i * 16 + (lane >> 2)) * DD
                    + h * HD;
        size_t oB = oA + 8 * DD;
#pragma unroll
        for (int j = 0; j < 8; j++) {
            int d = 8 * j + 2 * (lane & 3);
            *(uint32_t*)(AOf + oA + d) = packh2(O[i][j][0] * iA, O[i][j][1] * iA);
            *(uint32_t*)(AOf + oB + d) = packh2(O[i][j][2] * iB, O[i][j][3] * iB);
        }
    }
}

// ---------------------------------------------------------------------------
extern "C" void kernel_launch(void* const* d_in, const int* in_sizes, int n_in,
                              void* d_out, int out_size)
{
    (void)in_sizes; (void)n_in; (void)out_size;
    const float* x         = (const float*)d_in[0];
    const float* attn_bias = (const float*)d_in[1];
    const float* qkv_w     = (const float*)d_in[2];
    const float* qkv_b     = (const float*)d_in[3];
    const float* out_w     = (const float*)d_in[4];
    const float* out_b     = (const float*)d_in[5];
    float* out = (float*)d_out;

    __half *af, *wf, *qf, *kf, *vf;
    cudaGetSymbolAddress((void**)&af, g_af);
    cudaGetSymbolAddress((void**)&wf, g_wf);
    cudaGetSymbolAddress((void**)&qf, g_qf);
    cudaGetSymbolAddress((void**)&kf, g_kf);
    cudaGetSymbolAddress((void**)&vf, g_vf);

    cudaFuncSetAttribute(gemm_mma_kernel,
                         cudaFuncAttributeMaxDynamicSharedMemorySize, SMEM_GEMM);
    cudaFuncSetAttribute(flash_mma_kernel,
                         cudaFuncAttributeMaxDynamicSharedMemorySize, FLASH_SMEM);

    // 1) cast x and qkv_w to fp16
    {
        int n4 = MM * GK / 4;
        convert_f16_kernel<<<(n4 + 255) / 256, 256>>>(x, af, n4);
        int w4 = DQKV * GK / 4;
        convert_f16_kernel<<<(w4 + 255) / 256, 256>>>(qkv_w, wf, w4);
    }
    // 2) QKV projection (single fp16); epilogue emits q/k/v fp16 [b,h,s,d]
    gemm_mma_kernel<<<dim3(DQKV / BN, MM / BM), 256, SMEM_GEMM>>>(
        af, wf, qkv_b, out /*unused*/, DQKV, 1);

    // 3) Flash attention, single-term fp16, m=32/warp -> ao fp16
    flash_mma_kernel<<<dim3(BB, HH, SS / 128), 128, FLASH_SMEM>>>(
        qf, kf, vf, attn_bias, af);

    // 4) cast out_w to fp16
    {
        int w4 = DD * DD / 4;
        convert_f16_kernel<<<(w4 + 255) / 256, 256>>>(out_w, wf, w4);
    }
    // 5) Output projection (single fp16) -> d_out
    gemm_mma_kernel<<<dim3(DD / BN, MM / BM), 256, SMEM_GEMM>>>(
        af, wf, out_b, out, DD, 0);
}

// round 13
// speedup vs baseline: 2.2503x; 1.0315x over previous
#include <cuda_runtime.h>
#include <cuda_bf16.h>
#include <cuda_fp16.h>
#include <cstdint>
#include <math.h>

// Problem constants
#define BB   4
#define SS   2048
#define DD   1024
#define HH   16
#define HD   64
#define DQKV 3072
#define MM   (BB*SS)          // 8192
#define GK   1024

// GEMM tiling (single-term fp16)
#define BM 128
#define BN 128
#define BK 32
#define NKT (GK/BK)           // 32
#define ROWH 40               // padded row stride in halfs (80B)
#define MATH (BM*ROWH)        // 5120 halfs per matrix tile
#define STAGEH (2*MATH)       // A + W per stage

// Flash smem layout: 3-stage ring, single-fp16 K and V per stage
#define FROWH 72                      // K/V row stride in halfs (144B)
#define FMATB (64*FROWH*2)            // 9216 B per 64x64 fp16 matrix
#define FKVB  (2*FMATB)               // 18432 B per stage (K, V)
#define FLASH_SMEM (3*FKVB)           // 55296 B -> 2 CTAs/SM
#define NFT (SS/64)                   // 32 key tiles
#define LOG2E 1.4426950408889634f
#define CSUB2 (6.0f * LOG2E)          // shift in log2 domain: p = 2^(s_l2 - C)

// Scratch (allocation-free: device globals)
__device__ __half g_af[(size_t)MM * GK];   // x fp16, then ao fp16 (reused)
__device__ __half g_wf[(size_t)DQKV * GK]; // qkv_w fp16, then out_w fp16
__device__ __half g_qf[(size_t)MM * DD];   // [b,h,s,d] fp16, q pre-scaled by 0.125*log2e
__device__ __half g_kf[(size_t)MM * DD];
__device__ __half g_vf[(size_t)MM * DD];

// ---------------------------------------------------------------------------
// PTX helpers (sm_80-portable: cp.async, ldmatrix, mma.sync, ex2.f16x2)
// ---------------------------------------------------------------------------
__device__ __forceinline__ uint32_t smem_u32(const void* p) {
    uint32_t a;
    asm("{ .reg .u64 t; cvta.to.shared.u64 t, %1; cvt.u32.u64 %0, t; }"
        : "=r"(a) : "l"(p));
    return a;
}
__device__ __forceinline__ void cp_async16(uint32_t dst, const void* src) {
    asm volatile("cp.async.cg.shared.global [%0], [%1], 16;" :: "r"(dst), "l"(src));
}
__device__ __forceinline__ void ldmx4(uint32_t* r, uint32_t addr) {
    asm volatile("ldmatrix.sync.aligned.m8n8.x4.shared.b16 {%0,%1,%2,%3}, [%4];"
                 : "=r"(r[0]), "=r"(r[1]), "=r"(r[2]), "=r"(r[3]) : "r"(addr));
}
__device__ __forceinline__ void ldmx4t(uint32_t* r, uint32_t addr) {
    asm volatile("ldmatrix.sync.aligned.m8n8.x4.trans.shared.b16 {%0,%1,%2,%3}, [%4];"
                 : "=r"(r[0]), "=r"(r[1]), "=r"(r[2]), "=r"(r[3]) : "r"(addr));
}
__device__ __forceinline__ void mma_f16(float* d, const uint32_t* a, const uint32_t* b) {
    asm("mma.sync.aligned.m16n8k16.row.col.f32.f16.f16.f32 "
        "{%0,%1,%2,%3}, {%4,%5,%6,%7}, {%8,%9}, {%0,%1,%2,%3};"
        : "+f"(d[0]), "+f"(d[1]), "+f"(d[2]), "+f"(d[3])
        : "r"(a[0]), "r"(a[1]), "r"(a[2]), "r"(a[3]), "r"(b[0]), "r"(b[1]));
}
__device__ __forceinline__ uint32_t packh2(float x, float y) {
    __half2 h = __floats2half2_rn(x, y);   // low = x, high = y
    return *reinterpret_cast<uint32_t*>(&h);
}
__device__ __forceinline__ uint32_t ex2h2(uint32_t x) {
    uint32_t r;
    asm("ex2.approx.f16x2 %0, %1;" : "=r"(r) : "r"(x));
    return r;
}

// ---------------------------------------------------------------------------
// fp32 -> fp16 cast (bulk)
// ---------------------------------------------------------------------------
__global__ __launch_bounds__(256) void convert_f16_kernel(
    const float* __restrict__ in, __half* __restrict__ o, int n4)
{
    int i = blockIdx.x * blockDim.x + threadIdx.x;
    if (i >= n4) return;
    float4 v = *(const float4*)(in + (size_t)i * 4);
    uint32_t* op = (uint32_t*)(o + (size_t)i * 4);
    op[0] = packh2(v.x, v.y);
    op[1] = packh2(v.z, v.w);
}

// ---------------------------------------------------------------------------
// HMMA GEMM (single fp16): C = A @ W^T + bias. mode 0: fp32 C.
// mode 1: QKV epilogue -> q(*0.125*log2e)/k/v fp16 in [b,h,s,d].
// ---------------------------------------------------------------------------
__global__ __launch_bounds__(256, 2) void gemm_mma_kernel(
    const __half* __restrict__ Af, const __half* __restrict__ Wf,
    const float* __restrict__ bias, float* __restrict__ C, int N, int mode)
{
    extern __shared__ __half smg[];
    const uint32_t sb = smem_u32(smg);
    const int tid  = threadIdx.x;
    const int wid  = tid >> 5;
    const int lane = tid & 31;
    const int m0 = blockIdx.y * BM;
    const int n0 = blockIdx.x * BN;
    const int warp_m = (wid >> 2) * 64;
    const int warp_n = (wid & 3) * 32;

    float acc[4][4][4];
#pragma unroll
    for (int i = 0; i < 4; i++)
#pragma unroll
        for (int j = 0; j < 4; j++)
#pragma unroll
            for (int r = 0; r < 4; r++) acc[i][j][r] = 0.f;

    auto load_stage = [&](int kt, int st) {
        const int kcol = kt * BK;
#pragma unroll
        for (int t = 0; t < 4; t++) {
            int c   = tid + t * 256;          // 0..1023
            int mat = c >> 9;                 // 0=A, 1=W
            int idx = c & 511;
            int row = idx >> 2;               // 0..127
            int c16 = idx & 3;                // 16B chunk along k
            int grow = (mat == 0 ? m0 : n0) + row;
            const __half* src = (mat == 0 ? Af : Wf) + (size_t)grow * GK + kcol + c16 * 8;
            uint32_t dst = sb + (uint32_t)(st * STAGEH + mat * MATH + row * ROWH + c16 * 8) * 2;
            cp_async16(dst, src);
        }
        asm volatile("cp.async.commit_group;" ::: "memory");
    };

    load_stage(0, 0);

    for (int kt = 0; kt < NKT; kt++) {
        const int st = kt & 1;
        if (kt + 1 < NKT) {
            load_stage(kt + 1, st ^ 1);
            asm volatile("cp.async.wait_group 1;" ::: "memory");
        } else {
            asm volatile("cp.async.wait_group 0;" ::: "memory");
        }
        __syncthreads();

        const uint32_t aB = sb + (uint32_t)(st * STAGEH) * 2;
        const uint32_t wB = aB + MATH * 2;

#pragma unroll
        for (int ks = 0; ks < 2; ks++) {
            const int kk = ks * 16;
            uint32_t a4[4][4], b4[4][2];
#pragma unroll
            for (int i = 0; i < 4; i++) {
                uint32_t off = (uint32_t)((warp_m + i * 16 + (lane & 15)) * ROWH
                                          + kk + (lane >> 4) * 8) * 2;
                ldmx4(a4[i], aB + off);
            }
#pragma unroll
            for (int jp2 = 0; jp2 < 2; jp2++) {
                int g = lane >> 3;
                uint32_t off = (uint32_t)((warp_n + (2 * jp2 + (g >> 1)) * 8
                                           + (lane & 7)) * ROWH
                                          + kk + (g & 1) * 8) * 2;
                uint32_t r4[4];
                ldmx4(r4, wB + off);
                b4[2 * jp2][0] = r4[0]; b4[2 * jp2][1] = r4[1];
                b4[2 * jp2 + 1][0] = r4[2]; b4[2 * jp2 + 1][1] = r4[3];
            }
#pragma unroll
            for (int i = 0; i < 4; i++)
#pragma unroll
                for (int j = 0; j < 4; j++) mma_f16(acc[i][j], a4[i], b4[j]);
        }
        __syncthreads();
    }

    if (mode == 0) {
#pragma unroll
        for (int i = 0; i < 4; i++) {
#pragma unroll
            for (int j = 0; j < 4; j++) {
                int m = m0 + warp_m + i * 16 + (lane >> 2);
                int n = n0 + warp_n + j * 8 + (lane & 3) * 2;
                float2 bv = *(const float2*)(bias + n);
                float2 o0 = { acc[i][j][0] + bv.x, acc[i][j][1] + bv.y };
                float2 o1 = { acc[i][j][2] + bv.x, acc[i][j][3] + bv.y };
                *(float2*)(C + (size_t)m * N + n) = o0;
                *(float2*)(C + (size_t)(m + 8) * N + n) = o1;
            }
        }
    } else {
#pragma unroll
        for (int i = 0; i < 4; i++) {
#pragma unroll
            for (int j = 0; j < 4; j++) {
                int m = m0 + warp_m + i * 16 + (lane >> 2);
                int n = n0 + warp_n + j * 8 + (lane & 3) * 2;
                float2 bv = *(const float2*)(bias + n);
                int sel = n >> 10;
                int hh  = (n & 1023) >> 6;
                int d   = n & 63;
                // q carries 0.125 * log2e so QK MMA accumulates log2-domain logits
                float sc = (sel == 0) ? (0.125f * LOG2E) : 1.0f;
                __half* dst = (sel == 0) ? g_qf : (sel == 1) ? g_kf : g_vf;
#pragma unroll
                for (int rr = 0; rr < 2; rr++) {
                    int mm = m + rr * 8;
                    float vx = (acc[i][j][rr * 2 + 0] + bv.x) * sc;
                    float vy = (acc[i][j][rr * 2 + 1] + bv.y) * sc;
                    size_t idx = (((size_t)(mm >> 11) * HH + hh) * SS + (mm & 2047)) * HD + d;
                    *(uint32_t*)(dst + idx) = packh2(vx, vy);
                }
            }
        }
    }
}
static constexpr int SMEM_GEMM = 2 * STAGEH * 2;  // 40960 B

// ---------------------------------------------------------------------------
// Flash attention: single-term fp16, m=32 per warp. Softmax in log2 domain:
// s accumulates (qk*scale + bias)*log2e - C; p = ex2.approx.f16x2 on packed
// pairs (result IS the P fragment). Row sums via ones-B-fragment MMA into
// fp32 accumulators (no FADDs, no final shuffles).
// ---------------------------------------------------------------------------
__global__ __launch_bounds__(128, 2) void flash_mma_kernel(
    const __half* __restrict__ Qf, const __half* __restrict__ Kf,
    const __half* __restrict__ Vf, const float* __restrict__ bias,
    __half* __restrict__ AOf)
{
    extern __shared__ char smc[];
    const uint32_t sb = smem_u32(smc);
    const int tid = threadIdx.x, wid = tid >> 5, lane = tid & 31;
    const int b = blockIdx.x, h = blockIdx.y, q0 = blockIdx.z * 128;
    const int warp_m = wid * 32;
    const size_t bh = ((size_t)b * HH + h) * SS;

    // ones B-fragment (n8 x k16 of 1.0h) for row-sum MMAs
    const uint32_t ones[2] = {0x3C003C00u, 0x3C003C00u};

    // Q fragments for two m16 tiles (fp16, pre-scaled by 0.125*log2e)
    uint32_t qf[2][4][4];
#pragma unroll
    for (int i = 0; i < 2; i++) {
        size_t rA = (bh + q0 + warp_m + i * 16 + (lane >> 2)) * HD;
        size_t rB = rA + 8 * HD;
        int c0 = 2 * (lane & 3);
#pragma unroll
        for (int t = 0; t < 4; t++) {
            qf[i][t][0] = *(const uint32_t*)(Qf + rA + 16 * t + c0);
            qf[i][t][1] = *(const uint32_t*)(Qf + rB + 16 * t + c0);
            qf[i][t][2] = *(const uint32_t*)(Qf + rA + 16 * t + 8 + c0);
            qf[i][t][3] = *(const uint32_t*)(Qf + rB + 16 * t + 8 + c0);
        }
    }

    // bias row pointers per m-tile
    const float* bp0[2];
    const float* bp1[2];
#pragma unroll
    for (int i = 0; i < 2; i++) {
        bp0[i] = bias + ((size_t)h * SS + q0 + warp_m + i * 16 + (lane >> 2)) * SS
                 + 2 * (lane & 3);
        bp1[i] = bp0[i] + 8 * SS;
    }

    float O[2][8][4];
#pragma unroll
    for (int i = 0; i < 2; i++)
#pragma unroll
        for (int j = 0; j < 8; j++)
#pragma unroll
            for (int r = 0; r < 4; r++) O[i][j][r] = 0.f;
    float lsum[2][4];
#pragma unroll
    for (int i = 0; i < 2; i++)
#pragma unroll
        for (int r = 0; r < 4; r++) lsum[i][r] = 0.f;

    // s[i][j][r] preloaded with bias*log2e - C (log2-domain)
    float s[2][8][4];
#pragma unroll
    for (int i = 0; i < 2; i++)
#pragma unroll
        for (int j = 0; j < 8; j++) {
            float2 b0 = *(const float2*)(bp0[i] + 8 * j);
            float2 b1 = *(const float2*)(bp1[i] + 8 * j);
            s[i][j][0] = fmaf(b0.x, LOG2E, -CSUB2);
            s[i][j][1] = fmaf(b0.y, LOG2E, -CSUB2);
            s[i][j][2] = fmaf(b1.x, LOG2E, -CSUB2);
            s[i][j][3] = fmaf(b1.y, LOG2E, -CSUB2);
        }

    auto load_stage = [&](int kt) {
        if (kt < NFT) {
            uint32_t base = sb + (kt % 3) * FKVB;
            int k0 = kt * 64;
#pragma unroll
            for (int t = 0; t < 8; t++) {
                int c = tid + t * 128;                   // 0..1023
                int mat = c >> 9;                        // 0=K, 1=V
                int idx = c & 511;
                int row = idx >> 3, ch = idx & 7;
                const __half* src = mat ? Vf : Kf;
                cp_async16(base + mat * FMATB + (uint32_t)(row * FROWH + ch * 8) * 2,
                           src + (bh + k0 + row) * HD + ch * 8);
            }
        }
        asm volatile("cp.async.commit_group;" ::: "memory");
    };

    load_stage(0);
    load_stage(1);

    const int krow = ((lane >> 4) & 1) * 8 + (lane & 7);
    const int kcol = ((lane >> 3) & 1) * 8;
    const int vrow = ((lane >> 3) & 1) * 8 + (lane & 7);
    const int vcol = ((lane >> 4) & 1) * 8;

    for (int kt = 0; kt < NFT; kt++) {
        __syncthreads();                  // all warps done with stage (kt-1)%3
        load_stage(kt + 2);
        asm volatile("cp.async.wait_group 2;" ::: "memory");  // stage kt ready

        const uint32_t kvb = sb + (kt % 3) * FKVB;

        // ---- S += Q K^T (log2 domain); K frags shared by both m-tiles ----
#pragma unroll
        for (int t = 0; t < 4; t++) {
#pragma unroll
            for (int c = 0; c < 4; c++) {     // 16-key chunks
                uint32_t addr = kvb + (uint32_t)((c * 16 + krow) * FROWH
                                                 + 16 * t + kcol) * 2;
                uint32_t k4[4];
                ldmx4(k4, addr);
                mma_f16(s[0][2 * c],     qf[0][t], k4);
                mma_f16(s[0][2 * c + 1], qf[0][t], k4 + 2);
                mma_f16(s[1][2 * c],     qf[1][t], k4);
                mma_f16(s[1][2 * c + 1], qf[1][t], k4 + 2);
            }
        }

        // ---- per 16-key chunk: pack -> ex2.f16x2 -> P frag; row sums via
        //      ones-MMA; PV MMAs; bias prefetch after last pack ----
#pragma unroll
        for (int t = 0; t < 4; t++) {
            uint32_t pf[2][4];
#pragma unroll
            for (int i = 0; i < 2; i++) {
                pf[i][0] = ex2h2(packh2(s[i][2 * t][0],     s[i][2 * t][1]));
                pf[i][1] = ex2h2(packh2(s[i][2 * t][2],     s[i][2 * t][3]));
                pf[i][2] = ex2h2(packh2(s[i][2 * t + 1][0], s[i][2 * t + 1][1]));
                pf[i][3] = ex2h2(packh2(s[i][2 * t + 1][2], s[i][2 * t + 1][3]));
                mma_f16(lsum[i], pf[i], ones);   // row sums
            }

            if (t == 3 && kt + 1 < NFT) {
                // all s consumed: prefetch next tile's bias (log2 domain)
                const int kn = (kt + 1) * 64;
#pragma unroll
                for (int i = 0; i < 2; i++)
#pragma unroll
                    for (int j = 0; j < 8; j++) {
                        float2 b0 = *(const float2*)(bp0[i] + kn + 8 * j);
                        float2 b1 = *(const float2*)(bp1[i] + kn + 8 * j);
                        s[i][j][0] = fmaf(b0.x, LOG2E, -CSUB2);
                        s[i][j][1] = fmaf(b0.y, LOG2E, -CSUB2);
                        s[i][j][2] = fmaf(b1.x, LOG2E, -CSUB2);
                        s[i][j][3] = fmaf(b1.y, LOG2E, -CSUB2);
                    }
            }
#pragma unroll
            for (int jp = 0; jp < 4; jp++) {
                uint32_t addr = kvb + FMATB
                    + (uint32_t)((16 * t + vrow) * FROWH + 16 * jp + vcol) * 2;
                uint32_t v4[4];
                ldmx4t(v4, addr);
                mma_f16(O[0][2 * jp],     pf[0], v4);
                mma_f16(O[0][2 * jp + 1], pf[0], v4 + 2);
                mma_f16(O[1][2 * jp],     pf[1], v4);
                mma_f16(O[1][2 * jp + 1], pf[1], v4 + 2);
            }
        }
    }

    // ---- epilogue: rows sums already per-lane in lsum (d0=row, d2=row+8) ----
#pragma unroll
    for (int i = 0; i < 2; i++) {
        float iA = 1.f / lsum[i][0], iB = 1.f / lsum[i][2];
        size_t oA = ((size_t)b * SS + q0 + warp_m + i * 16 + (lane >> 2)) * DD
                    + h * HD;
        size_t oB = oA + 8 * DD;
#pragma unroll
        for (int j = 0; j < 8; j++) {
            int d = 8 * j + 2 * (lane & 3);
            *(uint32_t*)(AOf + oA + d) = packh2(O[i][j][0] * iA, O[i][j][1] * iA);
            *(uint32_t*)(AOf + oB + d) = packh2(O[i][j][2] * iB, O[i][j][3] * iB);
        }
    }
}

// ---------------------------------------------------------------------------
extern "C" void kernel_launch(void* const* d_in, const int* in_sizes, int n_in,
                              void* d_out, int out_size)
{
    (void)in_sizes; (void)n_in; (void)out_size;
    const float* x         = (const float*)d_in[0];
    const float* attn_bias = (const float*)d_in[1];
    const float* qkv_w     = (const float*)d_in[2];
    const float* qkv_b     = (const float*)d_in[3];
    const float* out_w     = (const float*)d_in[4];
    const float* out_b     = (const float*)d_in[5];
    float* out = (float*)d_out;

    __half *af, *wf, *qf, *kf, *vf;
    cudaGetSymbolAddress((void**)&af, g_af);
    cudaGetSymbolAddress((void**)&wf, g_wf);
    cudaGetSymbolAddress((void**)&qf, g_qf);
    cudaGetSymbolAddress((void**)&kf, g_kf);
    cudaGetSymbolAddress((void**)&vf, g_vf);

    cudaFuncSetAttribute(gemm_mma_kernel,
                         cudaFuncAttributeMaxDynamicSharedMemorySize, SMEM_GEMM);
    cudaFuncSetAttribute(flash_mma_kernel,
                         cudaFuncAttributeMaxDynamicSharedMemorySize, FLASH_SMEM);

    // 1) cast x and qkv_w to fp16
    {
        int n4 = MM * GK / 4;
        convert_f16_kernel<<<(n4 + 255) / 256, 256>>>(x, af, n4);
        int w4 = DQKV * GK / 4;
        convert_f16_kernel<<<(w4 + 255) / 256, 256>>>(qkv_w, wf, w4);
    }
    // 2) QKV projection (single fp16); epilogue emits q/k/v fp16 [b,h,s,d]
    gemm_mma_kernel<<<dim3(DQKV / BN, MM / BM), 256, SMEM_GEMM>>>(
        af, wf, qkv_b, out /*unused*/, DQKV, 1);

    // 3) Flash attention, single-term fp16, log2-domain softmax -> ao fp16
    flash_mma_kernel<<<dim3(BB, HH, SS / 128), 128, FLASH_SMEM>>>(
        qf, kf, vf, attn_bias, af);

    // 4) cast out_w to fp16
    {
        int w4 = DD * DD / 4;
        convert_f16_kernel<<<(w4 + 255) / 256, 256>>>(out_w, wf, w4);
    }
    // 5) Output projection (single fp16) -> d_out
    gemm_mma_kernel<<<dim3(DD / BN, MM / BM), 256, SMEM_GEMM>>>(
        af, wf, out_b, out, DD, 0);
}